// round 8
// baseline (speedup 1.0000x reference)
#include <cuda_runtime.h>
#include <cstdint>
#include <cstddef>
#include <math.h>

#define FULLMASK 0xFFFFFFFFu

// ----------------------------- static scratch ------------------------------
__device__ __align__(16) unsigned       g_xp[8192 * 28];    // packed input rows
__device__ __align__(16) unsigned       g_a1[8192 * 400];   // L1 acts, bit c = channel
__device__ __align__(16) unsigned short g_a2[8192 * 144];   // L2 acts, bit c = channel

__device__ unsigned       g_w1p[32 * 9];     // [f][u], bits v (for thresh1)
__device__ unsigned       g_w2p[16 * 81];    // [f][tap], bits c (for thresh2 tail)
__device__ unsigned short g_w3p[8 * 81];     // [f][tap], bits c(16)
__device__ unsigned       g_wlp[10 * 4];     // [f][p], bit (c + 8q)
__device__ float          g_sbl[10];

__device__ __align__(16) signed char g_w1s8[32 * 128];      // [f][kk], kk=u*12+v padded
__device__ __align__(16) signed char g_w2s8[81 * 16 * 32];  // [tap][f][c]

__device__ int g_T[784];
__device__ int g_S1[400 * 32];
__device__ int g_S2[144 * 16];
__device__ int g_thr1[32], g_thr2[16], g_lim3[8];
__device__ int g_c1, g_c2;

// ------------------------------ mma helpers --------------------------------
__device__ __forceinline__ unsigned s2u(const void* p) {
    return (unsigned)__cvta_generic_to_shared(p);
}
__device__ __forceinline__ void ldsm4(unsigned r[4], unsigned a) {
    asm volatile("ldmatrix.sync.aligned.m8n8.x4.shared.b16 {%0,%1,%2,%3},[%4];"
        : "=r"(r[0]), "=r"(r[1]), "=r"(r[2]), "=r"(r[3]) : "r"(a));
}
__device__ __forceinline__ void ldsm2(unsigned r[2], unsigned a) {
    asm volatile("ldmatrix.sync.aligned.m8n8.x2.shared.b16 {%0,%1},[%2];"
        : "=r"(r[0]), "=r"(r[1]) : "r"(a));
}
__device__ __forceinline__ void imma(int c[4], const unsigned a[4], const unsigned b[2]) {
    asm volatile("mma.sync.aligned.m16n8k32.row.col.s32.s8.s8.s32 "
        "{%0,%1,%2,%3},{%4,%5,%6,%7},{%8,%9},{%0,%1,%2,%3};"
        : "+r"(c[0]), "+r"(c[1]), "+r"(c[2]), "+r"(c[3])
        : "r"(a[0]), "r"(a[1]), "r"(a[2]), "r"(a[3]), "r"(b[0]), "r"(b[1]));
}

// ------------------------------ zero ---------------------------------------
__global__ void zerok() {
    int t = blockIdx.x * 256 + threadIdx.x;
    if (t < 12800) g_S1[t] = 0;
    if (t < 2304)  g_S2[t] = 0;
    if (t < 784)   g_T[t]  = 0;
    if (t == 0) { g_c1 = 0; g_c2 = 0; }
}

// ------------------- binarize x + batch counts + weight prep ---------------
__global__ __launch_bounds__(256) void binxprep(
    const float* __restrict__ x,  const float* __restrict__ w1,
    const float* __restrict__ w2, const float* __restrict__ w3,
    const float* __restrict__ wl, const float* __restrict__ bl) {
    __shared__ int Ts[784];
    int tid = threadIdx.x;
    for (int t = tid; t < 784; t += 256) Ts[t] = 0;
    if (blockIdx.x == 0) {                 // weight packing piggybacks on block 0
        for (int idx = tid; idx < 2282; idx += 256) {
            if (idx < 288) {
                int f = idx / 9, u = idx % 9; unsigned m = 0;
                for (int v = 0; v < 9; v++)
                    if (w1[f * 81 + u * 9 + v] >= 0.f) m |= 1u << v;
                g_w1p[idx] = m;
            } else if (idx < 1584) {
                int e = idx - 288, f = e / 81, t2 = e % 81; unsigned m = 0;
                for (int c = 0; c < 32; c++)
                    if (w2[f * 2592 + c * 81 + t2] >= 0.f) m |= 1u << c;
                g_w2p[e] = m;
            } else if (idx < 2232) {
                int e = idx - 1584, f = e / 81, t3 = e % 81; unsigned m = 0;
                for (int c = 0; c < 16; c++)
                    if (w3[f * 1296 + c * 81 + t3] >= 0.f) m |= 1u << c;
                g_w3p[e] = (unsigned short)m;
            } else if (idx < 2272) {
                int e = idx - 2232, f = e / 4, p = e % 4; unsigned m = 0;
                for (int q = 0; q < 4; q++)
                    for (int c = 0; c < 8; c++)
                        if (wl[f * 128 + c * 16 + (4 * p + q)] >= 0.f) m |= 1u << (c + 8 * q);
                g_wlp[e] = m;
            } else {
                int f = idx - 2272;
                g_sbl[f] = (bl[f] >= 0.f) ? 1.f : -1.f;
            }
        }
        // s8 weights for IMMA
        for (int e = tid; e < 4096; e += 256) {         // w1: [f(32)][kk(128)]
            int f = e >> 7, kk = e & 127, u = kk / 12, v = kk % 12;
            g_w1s8[e] = (kk < 108 && v < 9) ? ((w1[f * 81 + u * 9 + v] >= 0.f) ? 1 : -1) : 0;
        }
        for (int e = tid; e < 41472; e += 256) {        // w2: [tap][f][c]
            int tap = e >> 9, rem = e & 511, f = rem >> 5, c = rem & 31;
            g_w2s8[e] = (w2[f * 2592 + c * 81 + tap] >= 0.f) ? 1 : -1;
        }
    }
    __syncthreads();
    int lane = tid & 31, w = tid >> 5;
    int n = blockIdx.x * 8 + w;
    const float* xi = x + (size_t)n * 784;
    unsigned myrow = 0;
    for (int row = 0; row < 28; row++) {
        float v = (lane < 28) ? xi[row * 28 + lane] : -1.f;
        unsigned m = __ballot_sync(FULLMASK, v >= 0.f);
        if (lane == row) myrow = m;
        if (lane < 28 && ((m >> lane) & 1u)) atomicAdd(&Ts[row * 28 + lane], 1);
    }
    if (lane < 28) g_xp[n * 28 + lane] = myrow;
    __syncthreads();
    for (int t = tid; t < 784; t += 256) atomicAdd(&g_T[t], Ts[t]);
}

// ------------------------------ thresh1 ------------------------------------
__global__ void thresh1() {
    __shared__ int Tc[784];
    __shared__ int R[28 * 9];
    __shared__ int A[81];
    int tid = threadIdx.x;
    for (int t = tid; t < 784; t += 256) Tc[t] = g_T[t];
    __syncthreads();
    for (int e = tid; e < 252; e += 256) {
        int r = e / 9, v = e % 9, s = 0;
        for (int j = 0; j < 20; j++) s += Tc[r * 28 + j + v];
        R[e] = s;
    }
    __syncthreads();
    for (int e = tid; e < 81; e += 256) {
        int u = e / 9, v = e % 9, s = 0;
        for (int i = 0; i < 20; i++) s += R[(i + u) * 9 + v];
        A[e] = s;
    }
    __syncthreads();
    if (tid < 32) {
        long long s = 0;
        for (int u = 0; u < 9; u++) {
            unsigned wrow = g_w1p[tid * 9 + u];
            for (int v = 0; v < 9; v++) {
                long long a = 2LL * A[u * 9 + v] - 3276800LL;
                s += ((wrow >> v) & 1u) ? a : -a;
            }
        }
        g_thr1[tid] = (int)ceil((double)s / 3276800.0);   // bit=1 iff y >= thr
    }
}

// ------------------------------ conv1 via IMMA -----------------------------
// M=400 px, N=32 f, K=108->128 (kk=u*12+v, zero padded). 160 thr, 1 img/block.
__global__ __launch_bounds__(160) void conv1k() {
    extern __shared__ __align__(16) char sm[];
    signed char* A  = (signed char*)sm;              // 400*144 = 57600 (row stride 144)
    signed char* Bs = (signed char*)(sm + 57600);    // 32*144  = 4608
    unsigned* a1tmp = (unsigned*)(sm + 62208);       // 1600
    unsigned* xr    = (unsigned*)(sm + 63808);       // 112
    unsigned* lut4  = (unsigned*)(sm + 63920);       // 64
    int* thr        = (int*)(sm + 63984);            // 128  (end 64112)
    int tid = threadIdx.x, lane = tid & 31, w = tid >> 5, n = blockIdx.x;

    if (tid < 28) xr[tid] = g_xp[n * 28 + tid];
    if (tid < 32) thr[tid] = g_thr1[tid];
    if (tid >= 32 && tid < 48) {
        int t = tid - 32; unsigned v = 0;
        for (int k = 0; k < 4; k++) v |= (((t >> k) & 1) ? 0x01u : 0xFFu) << (8 * k);
        lut4[t] = v;
    }
    for (int e = tid; e < 4096; e += 160) Bs[(e >> 7) * 144 + (e & 127)] = g_w1s8[e];
    for (int e = tid; e < 400; e += 160) a1tmp[e] = 0;
    __syncthreads();

    // build im2col A: row p, bytes kk=u*12+v = x[(i+u)][(j+v)] as +/-1
    for (int p = tid; p < 400; p += 160) {
        int i = p / 20, j = p % 20;
        unsigned* Arow = (unsigned*)(A + p * 144);
#pragma unroll
        for (int u = 0; u < 9; u++) {
            unsigned wv = (xr[i + u] >> j) & 0x1FFu;
            Arow[u * 3 + 0] = lut4[wv & 15u];
            Arow[u * 3 + 1] = lut4[(wv >> 4) & 15u];
            Arow[u * 3 + 2] = (wv & 0x100u) ? 0x00000001u : 0x000000FFu;
        }
#pragma unroll
        for (int q = 27; q < 36; q++) Arow[q] = 0;   // kk 108..143 zero
    }
    __syncthreads();

    // B fragments, all (kchunk, ntile) in registers
    unsigned bfr[4][4][2];
    {
        unsigned r = lane & 7, half = (lane >> 3) & 1;
#pragma unroll
        for (int kc = 0; kc < 4; kc++)
#pragma unroll
            for (int nt = 0; nt < 4; nt++)
                ldsm2(bfr[kc][nt], s2u(Bs + (nt * 8 + (int)r) * 144 + kc * 32 + half * 16));
    }

    unsigned abase = s2u(A) + (unsigned)((lane & 15) * 144 + (lane >> 4) * 16);
#pragma unroll 1
    for (int t5 = 0; t5 < 5; t5++) {
        int mt = w * 5 + t5;
        unsigned arow = abase + (unsigned)(mt * 16 * 144);
        unsigned af[4][4];
#pragma unroll
        for (int kc = 0; kc < 4; kc++) ldsm4(af[kc], arow + kc * 32);
#pragma unroll
        for (int nt = 0; nt < 4; nt++) {
            int c[4] = {0, 0, 0, 0};
#pragma unroll
            for (int kc = 0; kc < 4; kc++) imma(c, af[kc], bfr[kc][nt]);
            int f0 = nt * 8 + 2 * (lane & 3);
            int p0 = mt * 16 + (lane >> 2);
            unsigned v0 = ((unsigned)(c[0] >= thr[f0]) | ((unsigned)(c[1] >= thr[f0 + 1]) << 1)) << f0;
            unsigned v1 = ((unsigned)(c[2] >= thr[f0]) | ((unsigned)(c[3] >= thr[f0 + 1]) << 1)) << f0;
            atomicOr(&a1tmp[p0], v0);
            atomicOr(&a1tmp[p0 + 8], v1);
        }
    }
    __syncthreads();
    for (int e = tid; e < 400; e += 160) g_a1[n * 400 + e] = a1tmp[e];
}

// ---------------- suma1: count a1 bits; last block computes thresh2 --------
__global__ __launch_bounds__(256) void suma1k() {
    int tg = blockIdx.x * 256 + threadIdx.x;       // 25600 = 400 px * 64 chunks
    int p = tg % 400, chunk = tg / 400;
    int cnt[32];
#pragma unroll
    for (int c = 0; c < 32; c++) cnt[c] = 0;
    const unsigned* base = &g_a1[(size_t)chunk * 128 * 400 + p];
    for (int k = 0; k < 128; k++) {
        unsigned wd = base[k * 400];
#pragma unroll
        for (int c = 0; c < 32; c++) cnt[c] += (wd >> c) & 1u;
    }
#pragma unroll
    for (int c = 0; c < 32; c++) atomicAdd(&g_S1[p * 32 + c], cnt[c]);

    __shared__ int R[20 * 9 * 32];
    __shared__ int WS[2592];
    __shared__ int lastf;
    __threadfence();
    if (threadIdx.x == 0) lastf = (atomicAdd(&g_c1, 1) == (int)gridDim.x - 1);
    __syncthreads();
    if (!lastf) return;
    __threadfence();
    int tid = threadIdx.x;
    for (int e = tid; e < 5760; e += 256) {
        int c = e & 31, rv = e >> 5, r = rv / 9, v = rv % 9, s = 0;
        for (int j = 0; j < 12; j++) s += g_S1[(r * 20 + j + v) * 32 + c];
        R[e] = s;
    }
    __syncthreads();
    for (int e = tid; e < 2592; e += 256) {
        int c = e & 31, uv = e >> 5, u = uv / 9, v = uv % 9, s = 0;
        for (int i = 0; i < 12; i++) s += R[((i + u) * 9 + v) * 32 + c];
        WS[e] = 2 * s - 1179648;
    }
    __syncthreads();
    int lane = tid & 31, wp = tid >> 5;
    for (int ff = 0; ff < 2; ff++) {
        int f = wp * 2 + ff;
        long long s = 0;
        for (int t = lane; t < 81; t += 32) {
            unsigned wdw = g_w2p[f * 81 + t];
#pragma unroll
            for (int c = 0; c < 32; c++) {
                int term = WS[t * 32 + c];
                s += ((wdw >> c) & 1u) ? term : -term;
            }
        }
        for (int o = 16; o > 0; o >>= 1) s += __shfl_down_sync(FULLMASK, s, o);
        if (lane == 0) g_thr2[f] = (int)ceil((double)s / 1179648.0);
    }
}

// ------------------------------ conv2 via IMMA -----------------------------
// 2 imgs/block, 320 thr (10 warps). M=144->160 (pad), N=16, K-loop = 81 taps x 32ch.
__global__ __launch_bounds__(320) void conv2k() {
    extern __shared__ __align__(16) char sm[];
    signed char* A  = (signed char*)sm;              // 2 * 416 * 48 = 39936
    signed char* Bs = (signed char*)(sm + 39936);    // 1296 * 48 = 62208
    unsigned* a2tmp = (unsigned*)(sm + 102144);      // 2 * 160 * 4 = 1280
    unsigned* lut4  = (unsigned*)(sm + 103424);      // 64
    int* thr        = (int*)(sm + 103488);           // 64 (end 103552)
    int tid = threadIdx.x, lane = tid & 31, w = tid >> 5;
    int n0 = blockIdx.x * 2;

    if (tid < 16) {
        unsigned v = 0;
        for (int k = 0; k < 4; k++) v |= (((tid >> k) & 1) ? 0x01u : 0xFFu) << (8 * k);
        lut4[tid] = v;
    }
    if (tid >= 16 && tid < 32) thr[tid - 16] = g_thr2[tid - 16];
    for (int e = tid; e < 41472; e += 320) Bs[(e >> 5) * 48 + (e & 31)] = g_w2s8[e];
    a2tmp[tid] = 0;
    for (int e = tid; e < 256; e += 320) {           // zero pad rows 400..415
        int img = e >> 7, r = (e >> 3) & 15, q = e & 7;
        ((unsigned*)(A + img * 19968 + (400 + r) * 48))[q] = 0;
    }
    __syncthreads();

    for (int e = tid; e < 800; e += 320) {           // unpack a1 bits -> +/-1 bytes
        int img = e / 400, p = e % 400;
        unsigned wv = g_a1[(size_t)(n0 + img) * 400 + p];
        unsigned* Arow = (unsigned*)(A + img * 19968 + p * 48);
#pragma unroll
        for (int q = 0; q < 8; q++) Arow[q] = lut4[(wv >> (4 * q)) & 15u];
    }
    __syncthreads();

    int img = w / 5, wi = w % 5;                     // warp -> (image, 2 m-tiles)
    const signed char* Ai = A + img * 19968;
    unsigned base[2], msk[2];
#pragma unroll
    for (int t = 0; t < 2; t++) {
        int mt = wi * 2 + t;
        int p = mt * 16 + (lane & 15);
        int valid = (p < 144);
        int row = valid ? ((p / 12) * 20 + (p % 12)) : (400 + (lane & 15));
        base[t] = s2u(Ai + row * 48 + (lane >> 4) * 16);
        msk[t] = valid ? 0xFFFFFFFFu : 0u;
    }
    unsigned bbase = s2u(Bs) + (unsigned)((lane & 7) * 48 + ((lane >> 3) & 1) * 16);

    int acc[2][2][4];
#pragma unroll
    for (int t = 0; t < 2; t++)
#pragma unroll
        for (int nt = 0; nt < 2; nt++)
#pragma unroll
            for (int q = 0; q < 4; q++) acc[t][nt][q] = 0;

#pragma unroll 3
    for (int tap = 0; tap < 81; tap++) {
        int u = tap / 9, v = tap % 9;
        unsigned toff = (unsigned)((u * 20 + v) * 48);
        unsigned af0[4], af1[4], bf0[2], bf1[2];
        ldsm4(af0, base[0] + (toff & msk[0]));
        ldsm4(af1, base[1] + (toff & msk[1]));
        unsigned btap = bbase + (unsigned)(tap * 768);
        ldsm2(bf0, btap);
        ldsm2(bf1, btap + 384);
        imma(acc[0][0], af0, bf0); imma(acc[0][1], af0, bf1);
        imma(acc[1][0], af1, bf0); imma(acc[1][1], af1, bf1);
    }

#pragma unroll
    for (int t = 0; t < 2; t++) {
        int mt = wi * 2 + t;
#pragma unroll
        for (int nt = 0; nt < 2; nt++) {
            int f0 = nt * 8 + 2 * (lane & 3);
            int p0 = mt * 16 + (lane >> 2);
            unsigned v0 = ((unsigned)(acc[t][nt][0] >= thr[f0]) |
                           ((unsigned)(acc[t][nt][1] >= thr[f0 + 1]) << 1)) << f0;
            unsigned v1 = ((unsigned)(acc[t][nt][2] >= thr[f0]) |
                           ((unsigned)(acc[t][nt][3] >= thr[f0 + 1]) << 1)) << f0;
            if (p0 < 144)     atomicOr(&a2tmp[img * 160 + p0], v0);
            if (p0 + 8 < 144) atomicOr(&a2tmp[img * 160 + p0 + 8], v1);
        }
    }
    __syncthreads();
    for (int e = tid; e < 288; e += 320) {
        int im = e / 144, p = e % 144;
        g_a2[(size_t)(n0 + im) * 144 + p] = (unsigned short)a2tmp[im * 160 + p];
    }
}

// ---------------- suma2: count a2 bits; last block computes thresh3 --------
__global__ __launch_bounds__(256) void suma2k() {
    int tg = blockIdx.x * 256 + threadIdx.x;       // 9216 = 144 px * 64 chunks
    int p = tg % 144, chunk = tg / 144;
    int cnt[16];
#pragma unroll
    for (int c = 0; c < 16; c++) cnt[c] = 0;
    const unsigned short* base = &g_a2[(size_t)chunk * 128 * 144 + p];
    for (int k = 0; k < 128; k++) {
        unsigned wd = base[k * 144];
#pragma unroll
        for (int c = 0; c < 16; c++) cnt[c] += (wd >> c) & 1u;
    }
#pragma unroll
    for (int c = 0; c < 16; c++) atomicAdd(&g_S2[p * 16 + c], cnt[c]);

    __shared__ int WS[1296];
    __shared__ int lastf;
    __threadfence();
    if (threadIdx.x == 0) lastf = (atomicAdd(&g_c2, 1) == (int)gridDim.x - 1);
    __syncthreads();
    if (!lastf) return;
    __threadfence();
    int tid = threadIdx.x;
    for (int e = tid; e < 1296; e += 256) {
        int c = e & 15, uv = e >> 4, u = uv / 9, v = uv % 9, s = 0;
        for (int i = 0; i < 4; i++)
            for (int j = 0; j < 4; j++)
                s += g_S2[((i + u) * 12 + (j + v)) * 16 + c];
        WS[e] = 2 * s - 131072;
    }
    __syncthreads();
    int lane = tid & 31, f = tid >> 5;
    long long s = 0;
    for (int t = lane; t < 81; t += 32) {
        unsigned wdw = g_w3p[f * 81 + t];
#pragma unroll
        for (int c = 0; c < 16; c++) {
            int term = WS[(t << 4) + c];
            s += ((wdw >> c) & 1u) ? term : -term;
        }
    }
    for (int o = 16; o > 0; o >>= 1) s += __shfl_down_sync(FULLMASK, s, o);
    if (lane == 0) {
        int t3 = (int)ceil((double)s / 131072.0);
        g_lim3[f] = (1296 - t3) >> 1;      // popc form for conv34k
    }
}

// --------------- conv3 + binarize + linear layer, fused --------------------
__global__ __launch_bounds__(256) void conv34k(float* __restrict__ out) {
    __shared__ unsigned short xs[2][144];
    __shared__ unsigned short ws[8 * 88];
    __shared__ int lim[8];
    __shared__ unsigned a3s[2][4];
    int tid = threadIdx.x;
    int n0 = blockIdx.x * 2;
    for (int t = tid; t < 288; t += 256) {
        int img = t / 144, pp = t % 144;
        xs[img][pp] = g_a2[(size_t)(n0 + img) * 144 + pp];
    }
    for (int t = tid; t < 648; t += 256) {
        int f = t / 81, k = t % 81;
        ws[f * 88 + k] = g_w3p[t];
    }
    if (tid < 8) lim[tid] = g_lim3[tid];
    __syncthreads();
    int half = tid >> 7, ht = tid & 127;
    int f = ht & 7, pix = ht >> 3, i = pix >> 2, j = pix & 3;
    const unsigned short* xb = &xs[half][i * 12 + j];
    const unsigned short* wb = &ws[f * 88];
    int acc = 0;
#pragma unroll
    for (int u = 0; u < 9; u++)
#pragma unroll
        for (int v = 0; v < 9; v++)
            acc += __popc((unsigned)(xb[u * 12 + v] ^ wb[u * 9 + v]));
    unsigned bw = __ballot_sync(FULLMASK, acc <= lim[f]);
    if ((tid & 31) == 0) a3s[half][ht >> 5] = bw;
    __syncthreads();
    if (ht < 10) {
        const unsigned* wp = &g_wlp[ht * 4];
        int pop = 0;
#pragma unroll
        for (int p4 = 0; p4 < 4; p4++) pop += __popc(a3s[half][p4] ^ wp[p4]);
        out[(n0 + half) * 10 + ht] = (float)(128 - 2 * pop) + g_sbl[ht];
    }
}

// ------------------------------ launch -------------------------------------
extern "C" void kernel_launch(void* const* d_in, const int* in_sizes, int n_in,
                              void* d_out, int out_size) {
    (void)out_size;
    const float *x = 0, *w1 = 0, *w2 = 0, *w3 = 0, *wl = 0, *bl = 0;
    for (int i = 0; i < n_in; i++) {
        const float* p = (const float*)d_in[i];
        switch (in_sizes[i]) {
            case 6422528: x  = p; break;
            case 2592:    w1 = p; break;
            case 41472:   w2 = p; break;
            case 10368:   w3 = p; break;
            case 1280:    wl = p; break;
            case 10:      bl = p; break;
            default: break;   // b1/b2/b3 cancel under BN+sign
        }
    }
    cudaFuncSetAttribute(conv1k, cudaFuncAttributeMaxDynamicSharedMemorySize, 64128);
    cudaFuncSetAttribute(conv2k, cudaFuncAttributeMaxDynamicSharedMemorySize, 103552);

    zerok   <<<50,   256>>>();
    binxprep<<<1024, 256>>>(x, w1, w2, w3, wl, bl);
    thresh1 <<<1,    256>>>();
    conv1k  <<<8192, 160, 64128>>>();
    suma1k  <<<100,  256>>>();
    conv2k  <<<4096, 320, 103552>>>();
    suma2k  <<<36,   256>>>();
    conv34k <<<4096, 256>>>((float*)d_out);
}

// round 11
// speedup vs baseline: 2.0084x; 2.0084x over previous
#include <cuda_runtime.h>
#include <cstdint>
#include <cstddef>
#include <math.h>

#define FULLMASK 0xFFFFFFFFu

// ----------------------------- static scratch ------------------------------
__device__ __align__(16) unsigned       g_xp[8192 * 28];    // packed input rows
__device__ __align__(16) unsigned       g_a1[8192 * 400];   // L1 acts, bit c = channel
__device__ __align__(16) unsigned short g_a2[8192 * 144];   // L2 acts, bit c = channel

__device__ unsigned       g_w1p[32 * 9];     // [f][u], bits v
__device__ unsigned       g_w2p[16 * 81];    // [f][tap], bits c(32)
__device__ unsigned short g_w3p[8 * 81];     // [f][tap], bits c(16)
__device__ unsigned       g_wlp[10 * 4];     // [f][p], bit (c + 8q)
__device__ float          g_sbl[10];

__device__ int g_T[784];
__device__ int g_S1[400 * 32];
__device__ int g_S2[144 * 16];
__device__ int g_lim1[32], g_lim2[16], g_lim3[8];   // popc limits (acc <= lim)
__device__ int g_c1, g_c2;

// ------------------------------ zero ---------------------------------------
__global__ void zerok() {
    int t = blockIdx.x * 256 + threadIdx.x;
    if (t < 12800) g_S1[t] = 0;
    if (t < 2304)  g_S2[t] = 0;
    if (t < 784)   g_T[t]  = 0;
    if (t == 0) { g_c1 = 0; g_c2 = 0; }
}

// ------------------------------ weight prep --------------------------------
__global__ __launch_bounds__(256) void prepk(
    const float* __restrict__ w1, const float* __restrict__ w2,
    const float* __restrict__ w3, const float* __restrict__ wl,
    const float* __restrict__ bl) {
    int idx = blockIdx.x * 256 + threadIdx.x;
    if (idx < 288) {
        int f = idx / 9, u = idx % 9; unsigned m = 0;
        for (int v = 0; v < 9; v++)
            if (w1[f * 81 + u * 9 + v] >= 0.f) m |= 1u << v;
        g_w1p[idx] = m;
    } else if (idx < 1584) {
        int e = idx - 288, f = e / 81, t2 = e % 81; unsigned m = 0;
        for (int c = 0; c < 32; c++)
            if (w2[f * 2592 + c * 81 + t2] >= 0.f) m |= 1u << c;
        g_w2p[e] = m;
    } else if (idx < 2232) {
        int e = idx - 1584, f = e / 81, t3 = e % 81; unsigned m = 0;
        for (int c = 0; c < 16; c++)
            if (w3[f * 1296 + c * 81 + t3] >= 0.f) m |= 1u << c;
        g_w3p[e] = (unsigned short)m;
    } else if (idx < 2272) {
        int e = idx - 2232, f = e / 4, p = e % 4; unsigned m = 0;
        for (int q = 0; q < 4; q++)
            for (int c = 0; c < 8; c++)
                if (wl[f * 128 + c * 16 + (4 * p + q)] >= 0.f) m |= 1u << (c + 8 * q);
        g_wlp[e] = m;
    } else if (idx < 2282) {
        int f = idx - 2272;
        g_sbl[f] = (bl[f] >= 0.f) ? 1.f : -1.f;
    }
}

// ------------------- binarize x + batch counts -----------------------------
__global__ __launch_bounds__(256) void binxk(const float* __restrict__ x) {
    __shared__ int Ts[784];
    int tid = threadIdx.x;
    for (int t = tid; t < 784; t += 256) Ts[t] = 0;
    __syncthreads();
    int lane = tid & 31, w = tid >> 5;
    int n = blockIdx.x * 8 + w;
    const float* xi = x + (size_t)n * 784;
    for (int row = 0; row < 28; row++) {
        float v = (lane < 28) ? xi[row * 28 + lane] : -1.f;
        unsigned m = __ballot_sync(FULLMASK, v >= 0.f);
        if (lane == 0) g_xp[n * 28 + row] = m;
        if (lane < 28 && ((m >> lane) & 1u)) atomicAdd(&Ts[row * 28 + lane], 1);
    }
    __syncthreads();
    for (int t = tid; t < 784; t += 256) atomicAdd(&g_T[t], Ts[t]);
}

// ------------------------------ thresh1 ------------------------------------
__global__ void thresh1() {
    __shared__ int Tc[784];
    __shared__ int R[28 * 9];
    __shared__ int A[81];
    int tid = threadIdx.x;
    for (int t = tid; t < 784; t += 256) Tc[t] = g_T[t];
    __syncthreads();
    for (int e = tid; e < 252; e += 256) {
        int r = e / 9, v = e % 9, s = 0;
        for (int j = 0; j < 20; j++) s += Tc[r * 28 + j + v];
        R[e] = s;
    }
    __syncthreads();
    for (int e = tid; e < 81; e += 256) {
        int u = e / 9, v = e % 9, s = 0;
        for (int i = 0; i < 20; i++) s += R[(i + u) * 9 + v];
        A[e] = s;
    }
    __syncthreads();
    if (tid < 32) {
        long long s = 0;
        for (int u = 0; u < 9; u++) {
            unsigned wrow = g_w1p[tid * 9 + u];
            for (int v = 0; v < 9; v++) {
                long long a = 2LL * A[u * 9 + v] - 3276800LL;
                s += ((wrow >> v) & 1u) ? a : -a;
            }
        }
        int t1 = (int)ceil((double)s / 3276800.0);
        g_lim1[tid] = (81 - t1) >> 1;     // y>=t1  <=>  popc-acc <= lim
    }
}

// ------------------------------ conv1 --------------------------------------
// Warp = image. Phase 1: pack each 81-bit window into 3 smem words
// (3 x 9-bit slices per word). Phase 2: lane = filter, 3 popc per position,
// ballot emits the packed a1 word directly.
__global__ __launch_bounds__(256) void conv1k() {
    __shared__ unsigned win[8][1200];      // [warp][p*3+k]
    __shared__ unsigned xr[8][28];
    int tid = threadIdx.x, lane = tid & 31, w = tid >> 5;
    int n = blockIdx.x * 8 + w;
    if (lane < 28) xr[w][lane] = g_xp[n * 28 + lane];
    // per-lane filter weights packed the same 3-word way
    unsigned fw0, fw1, fw2;
    {
        const unsigned* wp = &g_w1p[lane * 9];
        fw0 = wp[0] | (wp[1] << 9) | (wp[2] << 18);
        fw1 = wp[3] | (wp[4] << 9) | (wp[5] << 18);
        fw2 = wp[6] | (wp[7] << 9) | (wp[8] << 18);
    }
    int mylim = g_lim1[lane];
    __syncwarp();

    const unsigned* xrw = xr[w];
    for (int p = lane; p < 400; p += 32) {
        int i = p / 20, j = p % 20;
        unsigned s0 = (xrw[i + 0] >> j) & 0x1FFu, s1 = (xrw[i + 1] >> j) & 0x1FFu;
        unsigned s2 = (xrw[i + 2] >> j) & 0x1FFu, s3 = (xrw[i + 3] >> j) & 0x1FFu;
        unsigned s4 = (xrw[i + 4] >> j) & 0x1FFu, s5 = (xrw[i + 5] >> j) & 0x1FFu;
        unsigned s6 = (xrw[i + 6] >> j) & 0x1FFu, s7 = (xrw[i + 7] >> j) & 0x1FFu;
        unsigned s8 = (xrw[i + 8] >> j) & 0x1FFu;
        win[w][p * 3 + 0] = s0 | (s1 << 9) | (s2 << 18);
        win[w][p * 3 + 1] = s3 | (s4 << 9) | (s5 << 18);
        win[w][p * 3 + 2] = s6 | (s7 << 9) | (s8 << 18);
    }
    __syncwarp();

    unsigned* outp = &g_a1[n * 400];
    const unsigned* wb = win[w];
    for (int i = 0; i < 20; i++) {
        unsigned myw = 0;
#pragma unroll
        for (int j = 0; j < 20; j++) {
            int p3 = (i * 20 + j) * 3;
            int acc = __popc(wb[p3] ^ fw0) + __popc(wb[p3 + 1] ^ fw1)
                    + __popc(wb[p3 + 2] ^ fw2);
            unsigned b = __ballot_sync(FULLMASK, acc <= mylim);
            if (lane == j) myw = b;
        }
        if (lane < 20) outp[i * 20 + lane] = myw;
    }
}

// ---------------- suma1: count a1 bits; last block -> g_lim2 ---------------
__global__ __launch_bounds__(256) void suma1k() {
    int tg = blockIdx.x * 256 + threadIdx.x;       // 25600 = 400 px * 64 chunks
    int p = tg % 400, chunk = tg / 400;
    int cnt[32];
#pragma unroll
    for (int c = 0; c < 32; c++) cnt[c] = 0;
    const unsigned* base = &g_a1[(size_t)chunk * 128 * 400 + p];
    for (int k = 0; k < 128; k++) {
        unsigned wd = base[k * 400];
#pragma unroll
        for (int c = 0; c < 32; c++) cnt[c] += (wd >> c) & 1u;
    }
#pragma unroll
    for (int c = 0; c < 32; c++) atomicAdd(&g_S1[p * 32 + c], cnt[c]);

    __shared__ int R[20 * 9 * 32];
    __shared__ int WS[2592];
    __shared__ int lastf;
    __threadfence();
    if (threadIdx.x == 0) lastf = (atomicAdd(&g_c1, 1) == (int)gridDim.x - 1);
    __syncthreads();
    if (!lastf) return;
    __threadfence();
    int tid = threadIdx.x;
    for (int e = tid; e < 5760; e += 256) {
        int c = e & 31, rv = e >> 5, r = rv / 9, v = rv % 9, s = 0;
        for (int j = 0; j < 12; j++) s += g_S1[(r * 20 + j + v) * 32 + c];
        R[e] = s;
    }
    __syncthreads();
    for (int e = tid; e < 2592; e += 256) {
        int c = e & 31, uv = e >> 5, u = uv / 9, v = uv % 9, s = 0;
        for (int i = 0; i < 12; i++) s += R[((i + u) * 9 + v) * 32 + c];
        WS[e] = 2 * s - 1179648;
    }
    __syncthreads();
    int lane = tid & 31, wp = tid >> 5;
    for (int ff = 0; ff < 2; ff++) {
        int f = wp * 2 + ff;
        long long s = 0;
        for (int t = lane; t < 81; t += 32) {
            unsigned wdw = g_w2p[f * 81 + t];
#pragma unroll
            for (int c = 0; c < 32; c++) {
                int term = WS[t * 32 + c];
                s += ((wdw >> c) & 1u) ? term : -term;
            }
        }
        for (int o = 16; o > 0; o >>= 1) s += __shfl_down_sync(FULLMASK, s, o);
        if (lane == 0) {
            int t2 = (int)ceil((double)s / 1179648.0);
            g_lim2[f] = (2592 - t2) >> 1;
        }
    }
}

// ------------------------------ conv2 --------------------------------------
// 192 threads, 1 image/block. Task = (f, i, j-quad): 16*12*3 = 576 = 192*3.
// Lane layout: f = t&15 (= lane&15), halves of the warp handle consecutive r.
__global__ __launch_bounds__(192) void conv2k() {
    __shared__ unsigned xs[400];
    __shared__ unsigned ws[1296];
    __shared__ int lim[16];
    int tid = threadIdx.x, lane = tid & 31, n = blockIdx.x;
    for (int t = tid; t < 400; t += 192) xs[t] = g_a1[(size_t)n * 400 + t];
    for (int t = tid; t < 1296; t += 192) ws[t] = g_w2p[t];
    if (tid < 16) lim[tid] = g_lim2[tid];
    __syncthreads();

#pragma unroll 1
    for (int k = 0; k < 3; k++) {
        int t = tid + k * 192;
        int f = t & 15, r = t >> 4;               // r in 0..35
        int i = r / 3, j4 = (r % 3) * 4;
        const unsigned* wb = &ws[f * 81];
        int a0 = 0, a1 = 0, a2 = 0, a3 = 0;
#pragma unroll 3
        for (int u = 0; u < 9; u++) {
            const unsigned* xrow = &xs[(i + u) * 20 + j4];
            unsigned xw[12];
#pragma unroll
            for (int v = 0; v < 12; v++) xw[v] = xrow[v];
#pragma unroll
            for (int v = 0; v < 9; v++) {
                unsigned wv = wb[u * 9 + v];
                a0 += __popc(xw[v + 0] ^ wv);
                a1 += __popc(xw[v + 1] ^ wv);
                a2 += __popc(xw[v + 2] ^ wv);
                a3 += __popc(xw[v + 3] ^ wv);
            }
        }
        int limf = lim[f];
        unsigned myword = 0;
        {
            unsigned b;
            b = __ballot_sync(FULLMASK, a0 <= limf);
            if ((lane & 15) == 0) myword = (lane < 16) ? (b & 0xFFFFu) : (b >> 16);
            b = __ballot_sync(FULLMASK, a1 <= limf);
            if ((lane & 15) == 1) myword = (lane < 16) ? (b & 0xFFFFu) : (b >> 16);
            b = __ballot_sync(FULLMASK, a2 <= limf);
            if ((lane & 15) == 2) myword = (lane < 16) ? (b & 0xFFFFu) : (b >> 16);
            b = __ballot_sync(FULLMASK, a3 <= limf);
            if ((lane & 15) == 3) myword = (lane < 16) ? (b & 0xFFFFu) : (b >> 16);
        }
        if ((lane & 15) < 4) {
            int pix = i * 12 + (r % 3) * 4 + (lane & 15);
            g_a2[(size_t)n * 144 + pix] = (unsigned short)myword;
        }
    }
}

// ---------------- suma2: count a2 bits; last block -> g_lim3 ---------------
__global__ __launch_bounds__(256) void suma2k() {
    int tg = blockIdx.x * 256 + threadIdx.x;       // 9216 = 144 px * 64 chunks
    int p = tg % 144, chunk = tg / 144;
    int cnt[16];
#pragma unroll
    for (int c = 0; c < 16; c++) cnt[c] = 0;
    const unsigned short* base = &g_a2[(size_t)chunk * 128 * 144 + p];
    for (int k = 0; k < 128; k++) {
        unsigned wd = base[k * 144];
#pragma unroll
        for (int c = 0; c < 16; c++) cnt[c] += (wd >> c) & 1u;
    }
#pragma unroll
    for (int c = 0; c < 16; c++) atomicAdd(&g_S2[p * 16 + c], cnt[c]);

    __shared__ int WS[1296];
    __shared__ int lastf;
    __threadfence();
    if (threadIdx.x == 0) lastf = (atomicAdd(&g_c2, 1) == (int)gridDim.x - 1);
    __syncthreads();
    if (!lastf) return;
    __threadfence();
    int tid = threadIdx.x;
    for (int e = tid; e < 1296; e += 256) {
        int c = e & 15, uv = e >> 4, u = uv / 9, v = uv % 9, s = 0;
        for (int i = 0; i < 4; i++)
            for (int j = 0; j < 4; j++)
                s += g_S2[((i + u) * 12 + (j + v)) * 16 + c];
        WS[e] = 2 * s - 131072;
    }
    __syncthreads();
    int lane = tid & 31, f = tid >> 5;
    long long s = 0;
    for (int t = lane; t < 81; t += 32) {
        unsigned wdw = g_w3p[f * 81 + t];
#pragma unroll
        for (int c = 0; c < 16; c++) {
            int term = WS[(t << 4) + c];
            s += ((wdw >> c) & 1u) ? term : -term;
        }
    }
    for (int o = 16; o > 0; o >>= 1) s += __shfl_down_sync(FULLMASK, s, o);
    if (lane == 0) {
        int t3 = (int)ceil((double)s / 131072.0);
        g_lim3[f] = (1296 - t3) >> 1;
    }
}

// --------------- conv3 + binarize + linear layer, fused --------------------
__global__ __launch_bounds__(256) void conv34k(float* __restrict__ out) {
    __shared__ unsigned short xs[2][144];
    __shared__ unsigned short ws[8 * 88];   // stride 88 kills bank conflicts
    __shared__ int lim[8];
    __shared__ unsigned a3s[2][4];
    int tid = threadIdx.x;
    int n0 = blockIdx.x * 2;
    for (int t = tid; t < 288; t += 256) {
        int img = t / 144, pp = t % 144;
        xs[img][pp] = g_a2[(size_t)(n0 + img) * 144 + pp];
    }
    for (int t = tid; t < 648; t += 256) {
        int f = t / 81, k = t % 81;
        ws[f * 88 + k] = g_w3p[t];
    }
    if (tid < 8) lim[tid] = g_lim3[tid];
    __syncthreads();
    int half = tid >> 7, ht = tid & 127;
    int f = ht & 7, pix = ht >> 3, i = pix >> 2, j = pix & 3;
    const unsigned short* xb = &xs[half][i * 12 + j];
    const unsigned short* wb = &ws[f * 88];
    int acc = 0;
#pragma unroll
    for (int u = 0; u < 9; u++)
#pragma unroll
        for (int v = 0; v < 9; v++)
            acc += __popc((unsigned)(xb[u * 12 + v] ^ wb[u * 9 + v]));
    // ballot word (pix>>2) with bit ((pix&3)*8+f) — exactly g_wlp layout
    unsigned bw = __ballot_sync(FULLMASK, acc <= lim[f]);
    if ((tid & 31) == 0) a3s[half][ht >> 5] = bw;
    __syncthreads();
    if (ht < 10) {
        const unsigned* wp = &g_wlp[ht * 4];
        int pop = 0;
#pragma unroll
        for (int p4 = 0; p4 < 4; p4++) pop += __popc(a3s[half][p4] ^ wp[p4]);
        out[(n0 + half) * 10 + ht] = (float)(128 - 2 * pop) + g_sbl[ht];
    }
}

// ------------------------------ launch -------------------------------------
// Inputs identified BY ELEMENT COUNT (all 9 distinct): robust to any order.
extern "C" void kernel_launch(void* const* d_in, const int* in_sizes, int n_in,
                              void* d_out, int out_size) {
    (void)out_size;
    const float *x = 0, *w1 = 0, *w2 = 0, *w3 = 0, *wl = 0, *bl = 0;
    for (int i = 0; i < n_in; i++) {
        const float* p = (const float*)d_in[i];
        switch (in_sizes[i]) {
            case 6422528: x  = p; break;
            case 2592:    w1 = p; break;
            case 41472:   w2 = p; break;
            case 10368:   w3 = p; break;
            case 1280:    wl = p; break;
            case 10:      bl = p; break;
            default: break;   // b1/b2/b3 cancel under BN+sign
        }
    }
    zerok   <<<50,   256>>>();
    prepk   <<<9,    256>>>(w1, w2, w3, wl, bl);
    binxk   <<<1024, 256>>>(x);
    thresh1 <<<1,    256>>>();
    conv1k  <<<1024, 256>>>();
    suma1k  <<<100,  256>>>();
    conv2k  <<<8192, 192>>>();
    suma2k  <<<36,   256>>>();
    conv34k <<<4096, 256>>>((float*)d_out);
}

// round 13
// speedup vs baseline: 2.0123x; 1.0020x over previous
#include <cuda_runtime.h>
#include <cstdint>
#include <cstddef>
#include <math.h>

#define FULLMASK 0xFFFFFFFFu

// ----------------------------- static scratch ------------------------------
__device__ __align__(16) unsigned       g_xp[8192 * 28];    // packed input rows
__device__ __align__(16) unsigned       g_a1[8192 * 400];   // L1 acts, bit c = channel
__device__ __align__(16) unsigned short g_a2[8192 * 144];   // L2 acts, bit c = channel

__device__ unsigned       g_w1p[32 * 9];     // [f][u], bits v
__device__ unsigned       g_w2p[16 * 81];    // [f][tap], bits c(32)
__device__ unsigned short g_w3p[8 * 81];     // [f][tap], bits c(16)
__device__ unsigned       g_wlp[10 * 4];     // [f][p], bit (c + 8q)
__device__ float          g_sbl[10];

__device__ int g_T[784];
__device__ int g_S1[400 * 32];
__device__ int g_S2[144 * 16];
__device__ int g_lim1[32], g_lim2[16], g_lim3[8];   // popc limits (acc <= lim)
__device__ int g_c1, g_c2;

// ------------------------------ zero ---------------------------------------
__global__ void zerok() {
    int t = blockIdx.x * 256 + threadIdx.x;
    if (t < 12800) g_S1[t] = 0;
    if (t < 2304)  g_S2[t] = 0;
    if (t < 784)   g_T[t]  = 0;
    if (t == 0) { g_c1 = 0; g_c2 = 0; }
}

// ------------------------------ weight prep --------------------------------
__global__ __launch_bounds__(256) void prepk(
    const float* __restrict__ w1, const float* __restrict__ w2,
    const float* __restrict__ w3, const float* __restrict__ wl,
    const float* __restrict__ bl) {
    int idx = blockIdx.x * 256 + threadIdx.x;
    if (idx < 288) {
        int f = idx / 9, u = idx % 9; unsigned m = 0;
        for (int v = 0; v < 9; v++)
            if (w1[f * 81 + u * 9 + v] >= 0.f) m |= 1u << v;
        g_w1p[idx] = m;
    } else if (idx < 1584) {
        int e = idx - 288, f = e / 81, t2 = e % 81; unsigned m = 0;
        for (int c = 0; c < 32; c++)
            if (w2[f * 2592 + c * 81 + t2] >= 0.f) m |= 1u << c;
        g_w2p[e] = m;
    } else if (idx < 2232) {
        int e = idx - 1584, f = e / 81, t3 = e % 81; unsigned m = 0;
        for (int c = 0; c < 16; c++)
            if (w3[f * 1296 + c * 81 + t3] >= 0.f) m |= 1u << c;
        g_w3p[e] = (unsigned short)m;
    } else if (idx < 2272) {
        int e = idx - 2232, f = e / 4, p = e % 4; unsigned m = 0;
        for (int q = 0; q < 4; q++)
            for (int c = 0; c < 8; c++)
                if (wl[f * 128 + c * 16 + (4 * p + q)] >= 0.f) m |= 1u << (c + 8 * q);
        g_wlp[e] = m;
    } else if (idx < 2282) {
        int f = idx - 2272;
        g_sbl[f] = (bl[f] >= 0.f) ? 1.f : -1.f;
    }
}

// ------------------- binarize x + batch counts -----------------------------
__global__ __launch_bounds__(256) void binxk(const float* __restrict__ x) {
    __shared__ int Ts[784];
    int tid = threadIdx.x;
    for (int t = tid; t < 784; t += 256) Ts[t] = 0;
    __syncthreads();
    int lane = tid & 31, w = tid >> 5;
    int n = blockIdx.x * 8 + w;
    const float* xi = x + (size_t)n * 784;
    for (int row = 0; row < 28; row++) {
        float v = (lane < 28) ? xi[row * 28 + lane] : -1.f;
        unsigned m = __ballot_sync(FULLMASK, v >= 0.f);
        if (lane == 0) g_xp[n * 28 + row] = m;
        if (lane < 28 && ((m >> lane) & 1u)) atomicAdd(&Ts[row * 28 + lane], 1);
    }
    __syncthreads();
    for (int t = tid; t < 784; t += 256) atomicAdd(&g_T[t], Ts[t]);
}

// ------------------------------ thresh1 ------------------------------------
__global__ void thresh1() {
    __shared__ int Tc[784];
    __shared__ int R[28 * 9];
    __shared__ int A[81];
    int tid = threadIdx.x;
    for (int t = tid; t < 784; t += 256) Tc[t] = g_T[t];
    __syncthreads();
    for (int e = tid; e < 252; e += 256) {
        int r = e / 9, v = e % 9, s = 0;
        for (int j = 0; j < 20; j++) s += Tc[r * 28 + j + v];
        R[e] = s;
    }
    __syncthreads();
    for (int e = tid; e < 81; e += 256) {
        int u = e / 9, v = e % 9, s = 0;
        for (int i = 0; i < 20; i++) s += R[(i + u) * 9 + v];
        A[e] = s;
    }
    __syncthreads();
    if (tid < 32) {
        long long s = 0;
        for (int u = 0; u < 9; u++) {
            unsigned wrow = g_w1p[tid * 9 + u];
            for (int v = 0; v < 9; v++) {
                long long a = 2LL * A[u * 9 + v] - 3276800LL;
                s += ((wrow >> v) & 1u) ? a : -a;
            }
        }
        int t1 = (int)ceil((double)s / 3276800.0);
        g_lim1[tid] = (81 - t1) >> 1;     // y>=t1  <=>  popc-acc <= lim
    }
}

// ------------------------------ conv1 --------------------------------------
// Warp = image. Phase 1: pack each 81-bit window into 3 smem words
// (3 x 9-bit slices per word). Phase 2: lane = filter, 3 popc per position,
// ballot emits the packed a1 word directly.
__global__ __launch_bounds__(256) void conv1k() {
    __shared__ unsigned win[8][1200];      // [warp][p*3+k]
    __shared__ unsigned xr[8][28];
    int tid = threadIdx.x, lane = tid & 31, w = tid >> 5;
    int n = blockIdx.x * 8 + w;
    if (lane < 28) xr[w][lane] = g_xp[n * 28 + lane];
    unsigned fw0, fw1, fw2;
    {
        const unsigned* wp = &g_w1p[lane * 9];
        fw0 = wp[0] | (wp[1] << 9) | (wp[2] << 18);
        fw1 = wp[3] | (wp[4] << 9) | (wp[5] << 18);
        fw2 = wp[6] | (wp[7] << 9) | (wp[8] << 18);
    }
    int mylim = g_lim1[lane];
    __syncwarp();

    const unsigned* xrw = xr[w];
    for (int p = lane; p < 400; p += 32) {
        int i = p / 20, j = p % 20;
        unsigned s0 = (xrw[i + 0] >> j) & 0x1FFu, s1 = (xrw[i + 1] >> j) & 0x1FFu;
        unsigned s2 = (xrw[i + 2] >> j) & 0x1FFu, s3 = (xrw[i + 3] >> j) & 0x1FFu;
        unsigned s4 = (xrw[i + 4] >> j) & 0x1FFu, s5 = (xrw[i + 5] >> j) & 0x1FFu;
        unsigned s6 = (xrw[i + 6] >> j) & 0x1FFu, s7 = (xrw[i + 7] >> j) & 0x1FFu;
        unsigned s8 = (xrw[i + 8] >> j) & 0x1FFu;
        win[w][p * 3 + 0] = s0 | (s1 << 9) | (s2 << 18);
        win[w][p * 3 + 1] = s3 | (s4 << 9) | (s5 << 18);
        win[w][p * 3 + 2] = s6 | (s7 << 9) | (s8 << 18);
    }
    __syncwarp();

    unsigned* outp = &g_a1[n * 400];
    const unsigned* wb = win[w];
    for (int i = 0; i < 20; i++) {
        unsigned myw = 0;
#pragma unroll
        for (int j = 0; j < 20; j++) {
            int p3 = (i * 20 + j) * 3;
            int acc = __popc(wb[p3] ^ fw0) + __popc(wb[p3 + 1] ^ fw1)
                    + __popc(wb[p3 + 2] ^ fw2);
            unsigned b = __ballot_sync(FULLMASK, acc <= mylim);
            if (lane == j) myw = b;
        }
        if (lane < 20) outp[i * 20 + lane] = myw;
    }
}

// ---------------- suma1: count a1 bits; last block -> g_lim2 ---------------
__global__ __launch_bounds__(256) void suma1k() {
    int tg = blockIdx.x * 256 + threadIdx.x;       // 25600 = 400 px * 64 chunks
    int p = tg % 400, chunk = tg / 400;
    int cnt[32];
#pragma unroll
    for (int c = 0; c < 32; c++) cnt[c] = 0;
    const unsigned* base = &g_a1[(size_t)chunk * 128 * 400 + p];
    for (int k = 0; k < 128; k++) {
        unsigned wd = base[k * 400];
#pragma unroll
        for (int c = 0; c < 32; c++) cnt[c] += (wd >> c) & 1u;
    }
#pragma unroll
    for (int c = 0; c < 32; c++) atomicAdd(&g_S1[p * 32 + c], cnt[c]);

    __shared__ int R[20 * 9 * 32];
    __shared__ int WS[2592];
    __shared__ int lastf;
    __threadfence();
    if (threadIdx.x == 0) lastf = (atomicAdd(&g_c1, 1) == (int)gridDim.x - 1);
    __syncthreads();
    if (!lastf) return;
    __threadfence();
    int tid = threadIdx.x;
    for (int e = tid; e < 5760; e += 256) {
        int c = e & 31, rv = e >> 5, r = rv / 9, v = rv % 9, s = 0;
        for (int j = 0; j < 12; j++) s += g_S1[(r * 20 + j + v) * 32 + c];
        R[e] = s;
    }
    __syncthreads();
    for (int e = tid; e < 2592; e += 256) {
        int c = e & 31, uv = e >> 5, u = uv / 9, v = uv % 9, s = 0;
        for (int i = 0; i < 12; i++) s += R[((i + u) * 9 + v) * 32 + c];
        WS[e] = 2 * s - 1179648;
    }
    __syncthreads();
    int lane = tid & 31, wp = tid >> 5;
    for (int ff = 0; ff < 2; ff++) {
        int f = wp * 2 + ff;
        long long s = 0;
        for (int t = lane; t < 81; t += 32) {
            unsigned wdw = g_w2p[f * 81 + t];
#pragma unroll
            for (int c = 0; c < 32; c++) {
                int term = WS[t * 32 + c];
                s += ((wdw >> c) & 1u) ? term : -term;
            }
        }
        for (int o = 16; o > 0; o >>= 1) s += __shfl_down_sync(FULLMASK, s, o);
        if (lane == 0) {
            int t2 = (int)ceil((double)s / 1179648.0);
            g_lim2[f] = (2592 - t2) >> 1;
        }
    }
}

// ------------------------------ conv2 --------------------------------------
// 192 threads, 1 image/block, 1 task/thread: task = (f, row-pair, j-half).
// warp = row-pair (i0 = warp*2), half-warp = j-half, lane&15 = filter.
// Rotating 3-buffer register rows: per u only 1 new row load (14 LDS)
// + 9 weight LDS for 108 popc.
__global__ __launch_bounds__(192) void conv2k() {
    __shared__ unsigned xs[440];           // 400 + pad (prefetch overrun harmless)
    __shared__ unsigned ws[1296];
    __shared__ int lim[16];
    int tid = threadIdx.x, lane = tid & 31, n = blockIdx.x;
    for (int t = tid; t < 400; t += 192) xs[t] = g_a1[(size_t)n * 400 + t];
    for (int t = tid; t < 1296; t += 192) ws[t] = g_w2p[t];
    if (tid < 16) lim[tid] = g_lim2[tid];
    __syncthreads();

    int f = tid & 15;
    int jh = (tid >> 4) & 1;
    int ip = tid >> 5;                     // warp id = row-pair 0..5
    int i0 = ip * 2;
    const unsigned* wb = &ws[f * 81];
    const unsigned* xbase = &xs[i0 * 20 + jh * 6];

    unsigned rb0[14], rb1[14], rb2[14];
    int at[6], ab[6];
#pragma unroll
    for (int k = 0; k < 6; k++) { at[k] = 0; ab[k] = 0; }
#pragma unroll
    for (int v = 0; v < 14; v++) { rb0[v] = xbase[v]; rb1[v] = xbase[20 + v]; }

#define C2BODY(TP, BT, NX, U)                                            \
    {                                                                    \
        _Pragma("unroll")                                                \
        for (int v = 0; v < 14; v++) NX[v] = xbase[((U) + 2) * 20 + v];  \
        _Pragma("unroll")                                                \
        for (int v = 0; v < 9; v++) {                                    \
            unsigned wv = wb[(U) * 9 + v];                               \
            _Pragma("unroll")                                            \
            for (int jj = 0; jj < 6; jj++) {                             \
                at[jj] += __popc(TP[jj + v] ^ wv);                       \
                ab[jj] += __popc(BT[jj + v] ^ wv);                       \
            }                                                            \
        }                                                                \
    }

#pragma unroll 1
    for (int uu = 0; uu < 9; uu += 3) {
        C2BODY(rb0, rb1, rb2, uu + 0);
        C2BODY(rb1, rb2, rb0, uu + 1);
        C2BODY(rb2, rb0, rb1, uu + 2);
    }
#undef C2BODY

    int limf = lim[f];
    unsigned myword = 0;
#pragma unroll
    for (int k = 0; k < 6; k++) {
        unsigned b = __ballot_sync(FULLMASK, at[k] <= limf);
        if ((lane & 15) == k) myword = (lane < 16) ? (b & 0xFFFFu) : (b >> 16);
    }
#pragma unroll
    for (int k = 0; k < 6; k++) {
        unsigned b = __ballot_sync(FULLMASK, ab[k] <= limf);
        if ((lane & 15) == k + 6) myword = (lane < 16) ? (b & 0xFFFFu) : (b >> 16);
    }
    int kl = lane & 15;
    if (kl < 12) {
        int row = i0 + (kl >= 6);
        int col = jh * 6 + (kl % 6);
        g_a2[(size_t)n * 144 + row * 12 + col] = (unsigned short)myword;
    }
}

// ---------------- suma2: count a2 bits; last block -> g_lim3 ---------------
__global__ __launch_bounds__(256) void suma2k() {
    int tg = blockIdx.x * 256 + threadIdx.x;       // 9216 = 144 px * 64 chunks
    int p = tg % 144, chunk = tg / 144;
    int cnt[16];
#pragma unroll
    for (int c = 0; c < 16; c++) cnt[c] = 0;
    const unsigned short* base = &g_a2[(size_t)chunk * 128 * 144 + p];
    for (int k = 0; k < 128; k++) {
        unsigned wd = base[k * 144];
#pragma unroll
        for (int c = 0; c < 16; c++) cnt[c] += (wd >> c) & 1u;
    }
#pragma unroll
    for (int c = 0; c < 16; c++) atomicAdd(&g_S2[p * 16 + c], cnt[c]);

    __shared__ int WS[1296];
    __shared__ int lastf;
    __threadfence();
    if (threadIdx.x == 0) lastf = (atomicAdd(&g_c2, 1) == (int)gridDim.x - 1);
    __syncthreads();
    if (!lastf) return;
    __threadfence();
    int tid = threadIdx.x;
    for (int e = tid; e < 1296; e += 256) {
        int c = e & 15, uv = e >> 4, u = uv / 9, v = uv % 9, s = 0;
        for (int i = 0; i < 4; i++)
            for (int j = 0; j < 4; j++)
                s += g_S2[((i + u) * 12 + (j + v)) * 16 + c];
        WS[e] = 2 * s - 131072;
    }
    __syncthreads();
    int lane = tid & 31, f = tid >> 5;
    long long s = 0;
    for (int t = lane; t < 81; t += 32) {
        unsigned wdw = g_w3p[f * 81 + t];
#pragma unroll
        for (int c = 0; c < 16; c++) {
            int term = WS[(t << 4) + c];
            s += ((wdw >> c) & 1u) ? term : -term;
        }
    }
    for (int o = 16; o > 0; o >>= 1) s += __shfl_down_sync(FULLMASK, s, o);
    if (lane == 0) {
        int t3 = (int)ceil((double)s / 131072.0);
        g_lim3[f] = (1296 - t3) >> 1;
    }
}

// --------------- conv3 + binarize + linear layer, fused --------------------
__global__ __launch_bounds__(256) void conv34k(float* __restrict__ out) {
    __shared__ unsigned short xs[2][144];
    __shared__ unsigned short ws[8 * 88];   // stride 88 kills bank conflicts
    __shared__ int lim[8];
    __shared__ unsigned a3s[2][4];
    int tid = threadIdx.x;
    int n0 = blockIdx.x * 2;
    for (int t = tid; t < 288; t += 256) {
        int img = t / 144, pp = t % 144;
        xs[img][pp] = g_a2[(size_t)(n0 + img) * 144 + pp];
    }
    for (int t = tid; t < 648; t += 256) {
        int f = t / 81, k = t % 81;
        ws[f * 88 + k] = g_w3p[t];
    }
    if (tid < 8) lim[tid] = g_lim3[tid];
    __syncthreads();
    int half = tid >> 7, ht = tid & 127;
    int f = ht & 7, pix = ht >> 3, i = pix >> 2, j = pix & 3;
    const unsigned short* xb = &xs[half][i * 12 + j];
    const unsigned short* wb = &ws[f * 88];
    int acc = 0;
#pragma unroll
    for (int u = 0; u < 9; u++)
#pragma unroll
        for (int v = 0; v < 9; v++)
            acc += __popc((unsigned)(xb[u * 12 + v] ^ wb[u * 9 + v]));
    // ballot word (pix>>2) with bit ((pix&3)*8+f) — exactly g_wlp layout
    unsigned bw = __ballot_sync(FULLMASK, acc <= lim[f]);
    if ((tid & 31) == 0) a3s[half][ht >> 5] = bw;
    __syncthreads();
    if (ht < 10) {
        const unsigned* wp = &g_wlp[ht * 4];
        int pop = 0;
#pragma unroll
        for (int p4 = 0; p4 < 4; p4++) pop += __popc(a3s[half][p4] ^ wp[p4]);
        out[(n0 + half) * 10 + ht] = (float)(128 - 2 * pop) + g_sbl[ht];
    }
}

// ------------------------------ launch -------------------------------------
// Inputs identified BY ELEMENT COUNT (all 9 distinct): robust to any order.
extern "C" void kernel_launch(void* const* d_in, const int* in_sizes, int n_in,
                              void* d_out, int out_size) {
    (void)out_size;
    const float *x = 0, *w1 = 0, *w2 = 0, *w3 = 0, *wl = 0, *bl = 0;
    for (int i = 0; i < n_in; i++) {
        const float* p = (const float*)d_in[i];
        switch (in_sizes[i]) {
            case 6422528: x  = p; break;
            case 2592:    w1 = p; break;
            case 41472:   w2 = p; break;
            case 10368:   w3 = p; break;
            case 1280:    wl = p; break;
            case 10:      bl = p; break;
            default: break;   // b1/b2/b3 cancel under BN+sign
        }
    }
    zerok   <<<50,   256>>>();
    prepk   <<<9,    256>>>(w1, w2, w3, wl, bl);
    binxk   <<<1024, 256>>>(x);
    thresh1 <<<1,    256>>>();
    conv1k  <<<1024, 256>>>();
    suma1k  <<<100,  256>>>();
    conv2k  <<<8192, 192>>>();
    suma2k  <<<36,   256>>>();
    conv34k <<<4096, 256>>>((float*)d_out);
}

// round 14
// speedup vs baseline: 2.0514x; 1.0194x over previous
#include <cuda_runtime.h>
#include <cstdint>
#include <cstddef>
#include <math.h>

#define FULLMASK 0xFFFFFFFFu

// ----------------------------- static scratch ------------------------------
__device__ __align__(16) unsigned       g_xp[8192 * 28];    // packed input rows
__device__ __align__(16) unsigned       g_a1[8192 * 400];   // L1 acts, bit c = channel
__device__ __align__(16) unsigned short g_a2[8192 * 144];   // L2 acts, bit c = channel

__device__ unsigned       g_w1p[32 * 9];     // [f][u], bits v
__device__ unsigned       g_w2p[16 * 81];    // [f][tap], bits c(32)
__device__ unsigned short g_w3p[8 * 81];     // [f][tap], bits c(16)
__device__ unsigned       g_wlp[10 * 4];     // [f][p], bit (c + 8q)
__device__ float          g_sbl[10];

__device__ int g_T[784];
__device__ int g_S1[400 * 32];
__device__ int g_S2[144 * 16];
__device__ int g_lim1[32], g_lim2[16], g_lim3[8];   // popc limits (acc <= lim)
__device__ int g_c0, g_c1, g_c2;

// --------------------- prep: zero counters + pack weights ------------------
__global__ __launch_bounds__(256) void prepk(
    const float* __restrict__ w1, const float* __restrict__ w2,
    const float* __restrict__ w3, const float* __restrict__ wl,
    const float* __restrict__ bl) {
    int idx = blockIdx.x * 256 + threadIdx.x;
    if (idx < 12800) g_S1[idx] = 0;
    if (idx < 2304)  g_S2[idx] = 0;
    if (idx < 784)   g_T[idx]  = 0;
    if (idx == 0) { g_c0 = 0; g_c1 = 0; g_c2 = 0; }
    if (idx < 288) {
        int f = idx / 9, u = idx % 9; unsigned m = 0;
        for (int v = 0; v < 9; v++)
            if (w1[f * 81 + u * 9 + v] >= 0.f) m |= 1u << v;
        g_w1p[idx] = m;
    } else if (idx < 1584) {
        int e = idx - 288, f = e / 81, t2 = e % 81; unsigned m = 0;
        for (int c = 0; c < 32; c++)
            if (w2[f * 2592 + c * 81 + t2] >= 0.f) m |= 1u << c;
        g_w2p[e] = m;
    } else if (idx < 2232) {
        int e = idx - 1584, f = e / 81, t3 = e % 81; unsigned m = 0;
        for (int c = 0; c < 16; c++)
            if (w3[f * 1296 + c * 81 + t3] >= 0.f) m |= 1u << c;
        g_w3p[e] = (unsigned short)m;
    } else if (idx < 2272) {
        int e = idx - 2232, f = e / 4, p = e % 4; unsigned m = 0;
        for (int q = 0; q < 4; q++)
            for (int c = 0; c < 8; c++)
                if (wl[f * 128 + c * 16 + (4 * p + q)] >= 0.f) m |= 1u << (c + 8 * q);
        g_wlp[e] = m;
    } else if (idx < 2282) {
        int f = idx - 2272;
        g_sbl[f] = (bl[f] >= 0.f) ? 1.f : -1.f;
    }
}

// ------- binarize x + batch counts; LAST BLOCK computes g_lim1 -------------
__global__ __launch_bounds__(256) void binxk(const float* __restrict__ x) {
    __shared__ int Ts[784];
    __shared__ int R[28 * 9];
    __shared__ int A[81];
    __shared__ int lastf;
    int tid = threadIdx.x;
    for (int t = tid; t < 784; t += 256) Ts[t] = 0;
    __syncthreads();
    int lane = tid & 31, w = tid >> 5;
    int n = blockIdx.x * 8 + w;
    const float* xi = x + (size_t)n * 784;
    for (int row = 0; row < 28; row++) {
        float v = (lane < 28) ? xi[row * 28 + lane] : -1.f;
        unsigned m = __ballot_sync(FULLMASK, v >= 0.f);
        if (lane == 0) g_xp[n * 28 + row] = m;
        if (lane < 28 && ((m >> lane) & 1u)) atomicAdd(&Ts[row * 28 + lane], 1);
    }
    __syncthreads();
    for (int t = tid; t < 784; t += 256) atomicAdd(&g_T[t], Ts[t]);

    // last-block tail: thresh1
    __threadfence();
    if (tid == 0) lastf = (atomicAdd(&g_c0, 1) == (int)gridDim.x - 1);
    __syncthreads();
    if (!lastf) return;
    __threadfence();
    for (int t = tid; t < 784; t += 256) Ts[t] = g_T[t];
    __syncthreads();
    for (int e = tid; e < 252; e += 256) {
        int r = e / 9, v = e % 9, s = 0;
        for (int j = 0; j < 20; j++) s += Ts[r * 28 + j + v];
        R[e] = s;
    }
    __syncthreads();
    for (int e = tid; e < 81; e += 256) {
        int u = e / 9, v = e % 9, s = 0;
        for (int i = 0; i < 20; i++) s += R[(i + u) * 9 + v];
        A[e] = s;
    }
    __syncthreads();
    if (tid < 32) {
        long long s = 0;
        for (int u = 0; u < 9; u++) {
            unsigned wrow = g_w1p[tid * 9 + u];
            for (int v = 0; v < 9; v++) {
                long long a = 2LL * A[u * 9 + v] - 3276800LL;
                s += ((wrow >> v) & 1u) ? a : -a;
            }
        }
        int t1 = (int)ceil((double)s / 3276800.0);
        g_lim1[tid] = (81 - t1) >> 1;     // y>=t1  <=>  popc-acc <= lim
    }
}

// ------------------------------ conv1 --------------------------------------
// Warp = image. Phase 1: pack each 81-bit window into 3 smem words.
// Phase 2: lane = filter, 3 popc per position, ballot emits packed a1 word.
__global__ __launch_bounds__(256) void conv1k() {
    __shared__ unsigned win[8][1200];      // [warp][p*3+k]
    __shared__ unsigned xr[8][28];
    int tid = threadIdx.x, lane = tid & 31, w = tid >> 5;
    int n = blockIdx.x * 8 + w;
    if (lane < 28) xr[w][lane] = g_xp[n * 28 + lane];
    unsigned fw0, fw1, fw2;
    {
        const unsigned* wp = &g_w1p[lane * 9];
        fw0 = wp[0] | (wp[1] << 9) | (wp[2] << 18);
        fw1 = wp[3] | (wp[4] << 9) | (wp[5] << 18);
        fw2 = wp[6] | (wp[7] << 9) | (wp[8] << 18);
    }
    int mylim = g_lim1[lane];
    __syncwarp();

    const unsigned* xrw = xr[w];
    for (int p = lane; p < 400; p += 32) {
        int i = p / 20, j = p % 20;
        unsigned s0 = (xrw[i + 0] >> j) & 0x1FFu, s1 = (xrw[i + 1] >> j) & 0x1FFu;
        unsigned s2 = (xrw[i + 2] >> j) & 0x1FFu, s3 = (xrw[i + 3] >> j) & 0x1FFu;
        unsigned s4 = (xrw[i + 4] >> j) & 0x1FFu, s5 = (xrw[i + 5] >> j) & 0x1FFu;
        unsigned s6 = (xrw[i + 6] >> j) & 0x1FFu, s7 = (xrw[i + 7] >> j) & 0x1FFu;
        unsigned s8 = (xrw[i + 8] >> j) & 0x1FFu;
        win[w][p * 3 + 0] = s0 | (s1 << 9) | (s2 << 18);
        win[w][p * 3 + 1] = s3 | (s4 << 9) | (s5 << 18);
        win[w][p * 3 + 2] = s6 | (s7 << 9) | (s8 << 18);
    }
    __syncwarp();

    unsigned* outp = &g_a1[n * 400];
    const unsigned* wb = win[w];
    for (int i = 0; i < 20; i++) {
        unsigned myw = 0;
#pragma unroll
        for (int j = 0; j < 20; j++) {
            int p3 = (i * 20 + j) * 3;
            int acc = __popc(wb[p3] ^ fw0) + __popc(wb[p3 + 1] ^ fw1)
                    + __popc(wb[p3 + 2] ^ fw2);
            unsigned b = __ballot_sync(FULLMASK, acc <= mylim);
            if (lane == j) myw = b;
        }
        if (lane < 20) outp[i * 20 + lane] = myw;
    }
}

// ---------------- suma1: count a1 bits; last block -> g_lim2 ---------------
// 200 blocks: 400 px * 128 chunks of 64 images.
__global__ __launch_bounds__(256) void suma1k() {
    int tg = blockIdx.x * 256 + threadIdx.x;       // 51200
    int p = tg % 400, chunk = tg / 400;
    int cnt[32];
#pragma unroll
    for (int c = 0; c < 32; c++) cnt[c] = 0;
    const unsigned* base = &g_a1[(size_t)chunk * 64 * 400 + p];
    for (int k = 0; k < 64; k++) {
        unsigned wd = base[k * 400];
#pragma unroll
        for (int c = 0; c < 32; c++) cnt[c] += (wd >> c) & 1u;
    }
#pragma unroll
    for (int c = 0; c < 32; c++) atomicAdd(&g_S1[p * 32 + c], cnt[c]);

    __shared__ int R[20 * 9 * 32];
    __shared__ int WS[2592];
    __shared__ int lastf;
    __threadfence();
    if (threadIdx.x == 0) lastf = (atomicAdd(&g_c1, 1) == (int)gridDim.x - 1);
    __syncthreads();
    if (!lastf) return;
    __threadfence();
    int tid = threadIdx.x;
    for (int e = tid; e < 5760; e += 256) {
        int c = e & 31, rv = e >> 5, r = rv / 9, v = rv % 9, s = 0;
        for (int j = 0; j < 12; j++) s += g_S1[(r * 20 + j + v) * 32 + c];
        R[e] = s;
    }
    __syncthreads();
    for (int e = tid; e < 2592; e += 256) {
        int c = e & 31, uv = e >> 5, u = uv / 9, v = uv % 9, s = 0;
        for (int i = 0; i < 12; i++) s += R[((i + u) * 9 + v) * 32 + c];
        WS[e] = 2 * s - 1179648;
    }
    __syncthreads();
    int lane = tid & 31, wp = tid >> 5;
    for (int ff = 0; ff < 2; ff++) {
        int f = wp * 2 + ff;
        long long s = 0;
        for (int t = lane; t < 81; t += 32) {
            unsigned wdw = g_w2p[f * 81 + t];
#pragma unroll
            for (int c = 0; c < 32; c++) {
                int term = WS[t * 32 + c];
                s += ((wdw >> c) & 1u) ? term : -term;
            }
        }
        for (int o = 16; o > 0; o >>= 1) s += __shfl_down_sync(FULLMASK, s, o);
        if (lane == 0) {
            int t2 = (int)ceil((double)s / 1179648.0);
            g_lim2[f] = (2592 - t2) >> 1;
        }
    }
}

// ------------------------------ conv2 --------------------------------------
// 2 images/block, 384 threads, 1 task/thread: task = (img, f, row-pair, j-half).
// warp w: img = w/6, row-pair = w%6; half-warp = j-half, lane&15 = filter.
__global__ __launch_bounds__(384) void conv2k() {
    __shared__ unsigned xs[2][440];
    __shared__ unsigned ws[1296];
    __shared__ int lim[16];
    int tid = threadIdx.x, lane = tid & 31;
    int n0 = blockIdx.x * 2;
    for (int t = tid; t < 800; t += 384) {
        int im = t / 400;
        xs[im][t - im * 400] = g_a1[(size_t)n0 * 400 + t];
    }
    for (int t = tid; t < 1296; t += 384) ws[t] = g_w2p[t];
    if (tid < 16) lim[tid] = g_lim2[tid];
    __syncthreads();

    int f = tid & 15;
    int jh = (tid >> 4) & 1;
    int w = tid >> 5;
    int img = w / 6, ip = w - img * 6;     // row-pair 0..5
    int i0 = ip * 2;
    const unsigned* wb = &ws[f * 81];
    const unsigned* xbase = &xs[img][i0 * 20 + jh * 6];

    unsigned rb0[14], rb1[14], rb2[14];
    int at[6], ab[6];
#pragma unroll
    for (int k = 0; k < 6; k++) { at[k] = 0; ab[k] = 0; }
#pragma unroll
    for (int v = 0; v < 14; v++) { rb0[v] = xbase[v]; rb1[v] = xbase[20 + v]; }

#define C2BODY(TP, BT, NX, U)                                            \
    {                                                                    \
        _Pragma("unroll")                                                \
        for (int v = 0; v < 14; v++) NX[v] = xbase[((U) + 2) * 20 + v];  \
        _Pragma("unroll")                                                \
        for (int v = 0; v < 9; v++) {                                    \
            unsigned wv = wb[(U) * 9 + v];                               \
            _Pragma("unroll")                                            \
            for (int jj = 0; jj < 6; jj++) {                             \
                at[jj] += __popc(TP[jj + v] ^ wv);                       \
                ab[jj] += __popc(BT[jj + v] ^ wv);                       \
            }                                                            \
        }                                                                \
    }

#pragma unroll 1
    for (int uu = 0; uu < 9; uu += 3) {
        C2BODY(rb0, rb1, rb2, uu + 0);
        C2BODY(rb1, rb2, rb0, uu + 1);
        C2BODY(rb2, rb0, rb1, uu + 2);
    }
#undef C2BODY

    int limf = lim[f];
    unsigned myword = 0;
#pragma unroll
    for (int k = 0; k < 6; k++) {
        unsigned b = __ballot_sync(FULLMASK, at[k] <= limf);
        if ((lane & 15) == k) myword = (lane < 16) ? (b & 0xFFFFu) : (b >> 16);
    }
#pragma unroll
    for (int k = 0; k < 6; k++) {
        unsigned b = __ballot_sync(FULLMASK, ab[k] <= limf);
        if ((lane & 15) == k + 6) myword = (lane < 16) ? (b & 0xFFFFu) : (b >> 16);
    }
    int kl = lane & 15;
    if (kl < 12) {
        int row = i0 + (kl >= 6);
        int col = jh * 6 + (kl % 6);
        g_a2[(size_t)(n0 + img) * 144 + row * 12 + col] = (unsigned short)myword;
    }
}

// ---------------- suma2: count a2 bits; last block -> g_lim3 ---------------
// 72 blocks: 144 px * 128 chunks of 64 images.
__global__ __launch_bounds__(256) void suma2k() {
    int tg = blockIdx.x * 256 + threadIdx.x;       // 18432
    int p = tg % 144, chunk = tg / 144;
    int cnt[16];
#pragma unroll
    for (int c = 0; c < 16; c++) cnt[c] = 0;
    const unsigned short* base = &g_a2[(size_t)chunk * 64 * 144 + p];
    for (int k = 0; k < 64; k++) {
        unsigned wd = base[k * 144];
#pragma unroll
        for (int c = 0; c < 16; c++) cnt[c] += (wd >> c) & 1u;
    }
#pragma unroll
    for (int c = 0; c < 16; c++) atomicAdd(&g_S2[p * 16 + c], cnt[c]);

    __shared__ int WS[1296];
    __shared__ int lastf;
    __threadfence();
    if (threadIdx.x == 0) lastf = (atomicAdd(&g_c2, 1) == (int)gridDim.x - 1);
    __syncthreads();
    if (!lastf) return;
    __threadfence();
    int tid = threadIdx.x;
    for (int e = tid; e < 1296; e += 256) {
        int c = e & 15, uv = e >> 4, u = uv / 9, v = uv % 9, s = 0;
        for (int i = 0; i < 4; i++)
            for (int j = 0; j < 4; j++)
                s += g_S2[((i + u) * 12 + (j + v)) * 16 + c];
        WS[e] = 2 * s - 131072;
    }
    __syncthreads();
    int lane = tid & 31, f = tid >> 5;
    long long s = 0;
    for (int t = lane; t < 81; t += 32) {
        unsigned wdw = g_w3p[f * 81 + t];
#pragma unroll
        for (int c = 0; c < 16; c++) {
            int term = WS[(t << 4) + c];
            s += ((wdw >> c) & 1u) ? term : -term;
        }
    }
    for (int o = 16; o > 0; o >>= 1) s += __shfl_down_sync(FULLMASK, s, o);
    if (lane == 0) {
        int t3 = (int)ceil((double)s / 131072.0);
        g_lim3[f] = (1296 - t3) >> 1;
    }
}

// --------------- conv3 + binarize + linear layer, fused --------------------
__global__ __launch_bounds__(256) void conv34k(float* __restrict__ out) {
    __shared__ unsigned short xs[2][144];
    __shared__ unsigned short ws[8 * 88];   // stride 88 kills bank conflicts
    __shared__ int lim[8];
    __shared__ unsigned a3s[2][4];
    int tid = threadIdx.x;
    int n0 = blockIdx.x * 2;
    for (int t = tid; t < 288; t += 256) {
        int img = t / 144, pp = t % 144;
        xs[img][pp] = g_a2[(size_t)(n0 + img) * 144 + pp];
    }
    for (int t = tid; t < 648; t += 256) {
        int f = t / 81, k = t % 81;
        ws[f * 88 + k] = g_w3p[t];
    }
    if (tid < 8) lim[tid] = g_lim3[tid];
    __syncthreads();
    int half = tid >> 7, ht = tid & 127;
    int f = ht & 7, pix = ht >> 3, i = pix >> 2, j = pix & 3;
    const unsigned short* xb = &xs[half][i * 12 + j];
    const unsigned short* wb = &ws[f * 88];
    int acc = 0;
#pragma unroll
    for (int u = 0; u < 9; u++)
#pragma unroll
        for (int v = 0; v < 9; v++)
            acc += __popc((unsigned)(xb[u * 12 + v] ^ wb[u * 9 + v]));
    // ballot word (pix>>2) with bit ((pix&3)*8+f) — exactly g_wlp layout
    unsigned bw = __ballot_sync(FULLMASK, acc <= lim[f]);
    if ((tid & 31) == 0) a3s[half][ht >> 5] = bw;
    __syncthreads();
    if (ht < 10) {
        const unsigned* wp = &g_wlp[ht * 4];
        int pop = 0;
#pragma unroll
        for (int p4 = 0; p4 < 4; p4++) pop += __popc(a3s[half][p4] ^ wp[p4]);
        out[(n0 + half) * 10 + ht] = (float)(128 - 2 * pop) + g_sbl[ht];
    }
}

// ------------------------------ launch -------------------------------------
// Inputs identified BY ELEMENT COUNT (all 9 distinct): robust to any order.
extern "C" void kernel_launch(void* const* d_in, const int* in_sizes, int n_in,
                              void* d_out, int out_size) {
    (void)out_size;
    const float *x = 0, *w1 = 0, *w2 = 0, *w3 = 0, *wl = 0, *bl = 0;
    for (int i = 0; i < n_in; i++) {
        const float* p = (const float*)d_in[i];
        switch (in_sizes[i]) {
            case 6422528: x  = p; break;
            case 2592:    w1 = p; break;
            case 41472:   w2 = p; break;
            case 10368:   w3 = p; break;
            case 1280:    wl = p; break;
            case 10:      bl = p; break;
            default: break;   // b1/b2/b3 cancel under BN+sign
        }
    }
    prepk   <<<50,   256>>>(w1, w2, w3, wl, bl);
    binxk   <<<1024, 256>>>(x);
    conv1k  <<<1024, 256>>>();
    suma1k  <<<200,  256>>>();
    conv2k  <<<4096, 384>>>();
    suma2k  <<<72,   256>>>();
    conv34k <<<4096, 256>>>((float*)d_out);
}

// round 15
// speedup vs baseline: 2.1657x; 1.0557x over previous
#include <cuda_runtime.h>
#include <cstdint>
#include <cstddef>
#include <math.h>

#define FULLMASK 0xFFFFFFFFu

// ----------------------------- static scratch ------------------------------
__device__ __align__(16) unsigned       g_xp[8192 * 28];    // packed input rows
__device__ __align__(16) unsigned       g_a1[8192 * 400];   // L1 acts, bit c = channel
__device__ __align__(16) unsigned short g_a2[8192 * 144];   // L2 acts, bit c = channel

__device__ unsigned       g_w1p[32 * 9];     // [f][u], bits v
__device__ unsigned       g_w2p[16 * 81];    // [f][tap], bits c(32)
__device__ unsigned short g_w3p[8 * 81];     // [f][tap], bits c(16)
__device__ unsigned       g_wlp[10 * 4];     // [f][p], bit (c + 8q)
__device__ float          g_sbl[10];

__device__ int g_T[784];
__device__ int g_S1[400 * 32];
__device__ int g_S2[144 * 16];
__device__ int g_lim1[32], g_lim2[16], g_lim3[8];   // popc limits (acc <= lim)
__device__ int g_c0, g_c1, g_c2;

// --------------------- prep: zero counters + pack weights ------------------
__global__ __launch_bounds__(256) void prepk(
    const float* __restrict__ w1, const float* __restrict__ w2,
    const float* __restrict__ w3, const float* __restrict__ wl,
    const float* __restrict__ bl) {
    int idx = blockIdx.x * 256 + threadIdx.x;
    if (idx < 12800) g_S1[idx] = 0;
    if (idx < 2304)  g_S2[idx] = 0;
    if (idx < 784)   g_T[idx]  = 0;
    if (idx == 0) { g_c0 = 0; g_c1 = 0; g_c2 = 0; }
    if (idx < 288) {
        int f = idx / 9, u = idx % 9; unsigned m = 0;
        for (int v = 0; v < 9; v++)
            if (w1[f * 81 + u * 9 + v] >= 0.f) m |= 1u << v;
        g_w1p[idx] = m;
    } else if (idx < 1584) {
        int e = idx - 288, f = e / 81, t2 = e % 81; unsigned m = 0;
        for (int c = 0; c < 32; c++)
            if (w2[f * 2592 + c * 81 + t2] >= 0.f) m |= 1u << c;
        g_w2p[e] = m;
    } else if (idx < 2232) {
        int e = idx - 1584, f = e / 81, t3 = e % 81; unsigned m = 0;
        for (int c = 0; c < 16; c++)
            if (w3[f * 1296 + c * 81 + t3] >= 0.f) m |= 1u << c;
        g_w3p[e] = (unsigned short)m;
    } else if (idx < 2272) {
        int e = idx - 2232, f = e / 4, p = e % 4; unsigned m = 0;
        for (int q = 0; q < 4; q++)
            for (int c = 0; c < 8; c++)
                if (wl[f * 128 + c * 16 + (4 * p + q)] >= 0.f) m |= 1u << (c + 8 * q);
        g_wlp[e] = m;
    } else if (idx < 2282) {
        int f = idx - 2272;
        g_sbl[f] = (bl[f] >= 0.f) ? 1.f : -1.f;
    }
}

// ------- binarize x + batch counts; LAST BLOCK computes g_lim1 -------------
// Warp = image. Batch 28 loads up front (MLP), ballots back-to-back,
// pixel counts from ballot words (no smem atomics).
__global__ __launch_bounds__(256) void binxk(const float* __restrict__ x) {
    __shared__ unsigned mrow[8][28];
    __shared__ int Ts[784];
    __shared__ int R[28 * 9];
    __shared__ int A[81];
    __shared__ int lastf;
    int tid = threadIdx.x, lane = tid & 31, w = tid >> 5;
    int n = blockIdx.x * 8 + w;
    const float* xi = x + (size_t)n * 784;
    float va[28];
#pragma unroll
    for (int row = 0; row < 28; row++)
        va[row] = (lane < 28) ? xi[row * 28 + lane] : -1.f;
#pragma unroll
    for (int row = 0; row < 28; row++) {
        unsigned m = __ballot_sync(FULLMASK, va[row] >= 0.f);
        if (lane == 0) { g_xp[n * 28 + row] = m; mrow[w][row] = m; }
    }
    __syncthreads();
    for (int t = tid; t < 784; t += 256) {
        int row = t / 28, col = t % 28;
        int s = 0;
#pragma unroll
        for (int ww = 0; ww < 8; ww++) s += (mrow[ww][row] >> col) & 1;
        atomicAdd(&g_T[t], s);
    }

    // last-block tail: thresh1
    __threadfence();
    if (tid == 0) lastf = (atomicAdd(&g_c0, 1) == (int)gridDim.x - 1);
    __syncthreads();
    if (!lastf) return;
    __threadfence();
    for (int t = tid; t < 784; t += 256) Ts[t] = g_T[t];
    __syncthreads();
    for (int e = tid; e < 252; e += 256) {
        int r = e / 9, v = e % 9, s = 0;
#pragma unroll
        for (int j = 0; j < 20; j++) s += Ts[r * 28 + j + v];
        R[e] = s;
    }
    __syncthreads();
    for (int e = tid; e < 81; e += 256) {
        int u = e / 9, v = e % 9, s = 0;
#pragma unroll
        for (int i = 0; i < 20; i++) s += R[(i + u) * 9 + v];
        A[e] = s;
    }
    __syncthreads();
    if (tid < 32) {
        long long s = 0;
        for (int u = 0; u < 9; u++) {
            unsigned wrow = g_w1p[tid * 9 + u];
            for (int v = 0; v < 9; v++) {
                long long a = 2LL * A[u * 9 + v] - 3276800LL;
                s += ((wrow >> v) & 1u) ? a : -a;
            }
        }
        int t1 = (int)ceil((double)s / 3276800.0);
        g_lim1[tid] = (81 - t1) >> 1;     // y>=t1  <=>  popc-acc <= lim
    }
}

// ------------------------------ conv1 --------------------------------------
// Warp = image. Phase 1: pack each 81-bit window into 3 smem words.
// Phase 2: lane = filter, 3 popc per position, ballot emits packed a1 word.
__global__ __launch_bounds__(256) void conv1k() {
    __shared__ unsigned win[8][1200];      // [warp][p*3+k]
    __shared__ unsigned xr[8][28];
    int tid = threadIdx.x, lane = tid & 31, w = tid >> 5;
    int n = blockIdx.x * 8 + w;
    if (lane < 28) xr[w][lane] = g_xp[n * 28 + lane];
    unsigned fw0, fw1, fw2;
    {
        const unsigned* wp = &g_w1p[lane * 9];
        fw0 = wp[0] | (wp[1] << 9) | (wp[2] << 18);
        fw1 = wp[3] | (wp[4] << 9) | (wp[5] << 18);
        fw2 = wp[6] | (wp[7] << 9) | (wp[8] << 18);
    }
    int mylim = g_lim1[lane];
    __syncwarp();

    const unsigned* xrw = xr[w];
    for (int p = lane; p < 400; p += 32) {
        int i = p / 20, j = p % 20;
        unsigned s0 = (xrw[i + 0] >> j) & 0x1FFu, s1 = (xrw[i + 1] >> j) & 0x1FFu;
        unsigned s2 = (xrw[i + 2] >> j) & 0x1FFu, s3 = (xrw[i + 3] >> j) & 0x1FFu;
        unsigned s4 = (xrw[i + 4] >> j) & 0x1FFu, s5 = (xrw[i + 5] >> j) & 0x1FFu;
        unsigned s6 = (xrw[i + 6] >> j) & 0x1FFu, s7 = (xrw[i + 7] >> j) & 0x1FFu;
        unsigned s8 = (xrw[i + 8] >> j) & 0x1FFu;
        win[w][p * 3 + 0] = s0 | (s1 << 9) | (s2 << 18);
        win[w][p * 3 + 1] = s3 | (s4 << 9) | (s5 << 18);
        win[w][p * 3 + 2] = s6 | (s7 << 9) | (s8 << 18);
    }
    __syncwarp();

    unsigned* outp = &g_a1[n * 400];
    const unsigned* wb = win[w];
    for (int i = 0; i < 20; i++) {
        unsigned myw = 0;
#pragma unroll
        for (int j = 0; j < 20; j++) {
            int p3 = (i * 20 + j) * 3;
            int acc = __popc(wb[p3] ^ fw0) + __popc(wb[p3 + 1] ^ fw1)
                    + __popc(wb[p3 + 2] ^ fw2);
            unsigned b = __ballot_sync(FULLMASK, acc <= mylim);
            if (lane == j) myw = b;
        }
        if (lane < 20) outp[i * 20 + lane] = myw;
    }
}

// ---------------- suma1: count a1 bits; last block -> g_lim2 ---------------
// 200 blocks: 400 px * 128 chunks of 64 images. Byte-sliced counting:
// cnt8[c] bytes accumulate channels {c, c+8, c+16, c+24}; counts <= 64.
__global__ __launch_bounds__(256) void suma1k() {
    int tg = blockIdx.x * 256 + threadIdx.x;       // 51200
    int p = tg % 400, chunk = tg / 400;
    unsigned cnt8[8];
#pragma unroll
    for (int c = 0; c < 8; c++) cnt8[c] = 0;
    const unsigned* base = &g_a1[(size_t)chunk * 64 * 400 + p];
#pragma unroll 8
    for (int k = 0; k < 64; k++) {
        unsigned wd = base[k * 400];
#pragma unroll
        for (int c = 0; c < 8; c++) cnt8[c] += (wd >> c) & 0x01010101u;
    }
#pragma unroll
    for (int c = 0; c < 8; c++)
#pragma unroll
        for (int b = 0; b < 4; b++)
            atomicAdd(&g_S1[p * 32 + c + 8 * b], (int)((cnt8[c] >> (8 * b)) & 0xFFu));

    __shared__ int R[20 * 9 * 32];
    __shared__ int WS[2592];
    __shared__ int lastf;
    __threadfence();
    if (threadIdx.x == 0) lastf = (atomicAdd(&g_c1, 1) == (int)gridDim.x - 1);
    __syncthreads();
    if (!lastf) return;
    __threadfence();
    int tid = threadIdx.x;
    for (int e = tid; e < 5760; e += 256) {
        int c = e & 31, rv = e >> 5, r = rv / 9, v = rv % 9, s = 0;
#pragma unroll
        for (int j = 0; j < 12; j++) s += g_S1[(r * 20 + j + v) * 32 + c];
        R[e] = s;
    }
    __syncthreads();
    for (int e = tid; e < 2592; e += 256) {
        int c = e & 31, uv = e >> 5, u = uv / 9, v = uv % 9, s = 0;
#pragma unroll
        for (int i = 0; i < 12; i++) s += R[((i + u) * 9 + v) * 32 + c];
        WS[e] = 2 * s - 1179648;
    }
    __syncthreads();
    int lane = tid & 31, wp = tid >> 5;
    for (int ff = 0; ff < 2; ff++) {
        int f = wp * 2 + ff;
        long long s = 0;
        for (int t = lane; t < 81; t += 32) {
            unsigned wdw = g_w2p[f * 81 + t];
#pragma unroll
            for (int c = 0; c < 32; c++) {
                int term = WS[t * 32 + c];
                s += ((wdw >> c) & 1u) ? term : -term;
            }
        }
        for (int o = 16; o > 0; o >>= 1) s += __shfl_down_sync(FULLMASK, s, o);
        if (lane == 0) {
            int t2 = (int)ceil((double)s / 1179648.0);
            g_lim2[f] = (2592 - t2) >> 1;
        }
    }
}

// ------------------------------ conv2 --------------------------------------
// 2 images/block, 384 threads, 1 task/thread: task = (img, f, row-pair, j-half).
// warp w: img = w/6, row-pair = w%6; half-warp = j-half, lane&15 = filter.
__global__ __launch_bounds__(384) void conv2k() {
    __shared__ unsigned xs[2][440];
    __shared__ unsigned ws[1296];
    __shared__ int lim[16];
    int tid = threadIdx.x, lane = tid & 31;
    int n0 = blockIdx.x * 2;
    for (int t = tid; t < 800; t += 384) {
        int im = t / 400;
        xs[im][t - im * 400] = g_a1[(size_t)n0 * 400 + t];
    }
    for (int t = tid; t < 1296; t += 384) ws[t] = g_w2p[t];
    if (tid < 16) lim[tid] = g_lim2[tid];
    __syncthreads();

    int f = tid & 15;
    int jh = (tid >> 4) & 1;
    int w = tid >> 5;
    int img = w / 6, ip = w - img * 6;     // row-pair 0..5
    int i0 = ip * 2;
    const unsigned* wb = &ws[f * 81];
    const unsigned* xbase = &xs[img][i0 * 20 + jh * 6];

    unsigned rb0[14], rb1[14], rb2[14];
    int at[6], ab[6];
#pragma unroll
    for (int k = 0; k < 6; k++) { at[k] = 0; ab[k] = 0; }
#pragma unroll
    for (int v = 0; v < 14; v++) { rb0[v] = xbase[v]; rb1[v] = xbase[20 + v]; }

#define C2BODY(TP, BT, NX, U)                                            \
    {                                                                    \
        _Pragma("unroll")                                                \
        for (int v = 0; v < 14; v++) NX[v] = xbase[((U) + 2) * 20 + v];  \
        _Pragma("unroll")                                                \
        for (int v = 0; v < 9; v++) {                                    \
            unsigned wv = wb[(U) * 9 + v];                               \
            _Pragma("unroll")                                            \
            for (int jj = 0; jj < 6; jj++) {                             \
                at[jj] += __popc(TP[jj + v] ^ wv);                       \
                ab[jj] += __popc(BT[jj + v] ^ wv);                       \
            }                                                            \
        }                                                                \
    }

#pragma unroll 1
    for (int uu = 0; uu < 9; uu += 3) {
        C2BODY(rb0, rb1, rb2, uu + 0);
        C2BODY(rb1, rb2, rb0, uu + 1);
        C2BODY(rb2, rb0, rb1, uu + 2);
    }
#undef C2BODY

    int limf = lim[f];
    unsigned myword = 0;
#pragma unroll
    for (int k = 0; k < 6; k++) {
        unsigned b = __ballot_sync(FULLMASK, at[k] <= limf);
        if ((lane & 15) == k) myword = (lane < 16) ? (b & 0xFFFFu) : (b >> 16);
    }
#pragma unroll
    for (int k = 0; k < 6; k++) {
        unsigned b = __ballot_sync(FULLMASK, ab[k] <= limf);
        if ((lane & 15) == k + 6) myword = (lane < 16) ? (b & 0xFFFFu) : (b >> 16);
    }
    int kl = lane & 15;
    if (kl < 12) {
        int row = i0 + (kl >= 6);
        int col = jh * 6 + (kl % 6);
        g_a2[(size_t)(n0 + img) * 144 + row * 12 + col] = (unsigned short)myword;
    }
}

// ---------------- suma2: count a2 bits; last block -> g_lim3 ---------------
// 72 blocks: 144 px * 128 chunks of 64 images. Byte-sliced counting.
__global__ __launch_bounds__(256) void suma2k() {
    int tg = blockIdx.x * 256 + threadIdx.x;       // 18432
    int p = tg % 144, chunk = tg / 144;
    unsigned cnt8[8];
#pragma unroll
    for (int c = 0; c < 8; c++) cnt8[c] = 0;
    const unsigned short* base = &g_a2[(size_t)chunk * 64 * 144 + p];
#pragma unroll 8
    for (int k = 0; k < 64; k++) {
        unsigned wd = base[k * 144];
#pragma unroll
        for (int c = 0; c < 8; c++) cnt8[c] += (wd >> c) & 0x01010101u;
    }
#pragma unroll
    for (int c = 0; c < 8; c++)
#pragma unroll
        for (int b = 0; b < 2; b++)
            atomicAdd(&g_S2[p * 16 + c + 8 * b], (int)((cnt8[c] >> (8 * b)) & 0xFFu));

    __shared__ int WS[1296];
    __shared__ int lastf;
    __threadfence();
    if (threadIdx.x == 0) lastf = (atomicAdd(&g_c2, 1) == (int)gridDim.x - 1);
    __syncthreads();
    if (!lastf) return;
    __threadfence();
    int tid = threadIdx.x;
    for (int e = tid; e < 1296; e += 256) {
        int c = e & 15, uv = e >> 4, u = uv / 9, v = uv % 9, s = 0;
#pragma unroll
        for (int i = 0; i < 4; i++)
#pragma unroll
            for (int j = 0; j < 4; j++)
                s += g_S2[((i + u) * 12 + (j + v)) * 16 + c];
        WS[e] = 2 * s - 131072;
    }
    __syncthreads();
    int lane = tid & 31, f = tid >> 5;
    long long s = 0;
    for (int t = lane; t < 81; t += 32) {
        unsigned wdw = g_w3p[f * 81 + t];
#pragma unroll
        for (int c = 0; c < 16; c++) {
            int term = WS[(t << 4) + c];
            s += ((wdw >> c) & 1u) ? term : -term;
        }
    }
    for (int o = 16; o > 0; o >>= 1) s += __shfl_down_sync(FULLMASK, s, o);
    if (lane == 0) {
        int t3 = (int)ceil((double)s / 131072.0);
        g_lim3[f] = (1296 - t3) >> 1;
    }
}

// --------------- conv3 + binarize + linear layer, fused --------------------
__global__ __launch_bounds__(256) void conv34k(float* __restrict__ out) {
    __shared__ unsigned short xs[2][144];
    __shared__ unsigned short ws[8 * 88];   // stride 88 kills bank conflicts
    __shared__ int lim[8];
    __shared__ unsigned a3s[2][4];
    int tid = threadIdx.x;
    int n0 = blockIdx.x * 2;
    for (int t = tid; t < 288; t += 256) {
        int img = t / 144, pp = t % 144;
        xs[img][pp] = g_a2[(size_t)(n0 + img) * 144 + pp];
    }
    for (int t = tid; t < 648; t += 256) {
        int f = t / 81, k = t % 81;
        ws[f * 88 + k] = g_w3p[t];
    }
    if (tid < 8) lim[tid] = g_lim3[tid];
    __syncthreads();
    int half = tid >> 7, ht = tid & 127;
    int f = ht & 7, pix = ht >> 3, i = pix >> 2, j = pix & 3;
    const unsigned short* xb = &xs[half][i * 12 + j];
    const unsigned short* wb = &ws[f * 88];
    int acc = 0;
#pragma unroll
    for (int u = 0; u < 9; u++)
#pragma unroll
        for (int v = 0; v < 9; v++)
            acc += __popc((unsigned)(xb[u * 12 + v] ^ wb[u * 9 + v]));
    // ballot word (pix>>2) with bit ((pix&3)*8+f) — exactly g_wlp layout
    unsigned bw = __ballot_sync(FULLMASK, acc <= lim[f]);
    if ((tid & 31) == 0) a3s[half][ht >> 5] = bw;
    __syncthreads();
    if (ht < 10) {
        const unsigned* wp = &g_wlp[ht * 4];
        int pop = 0;
#pragma unroll
        for (int p4 = 0; p4 < 4; p4++) pop += __popc(a3s[half][p4] ^ wp[p4]);
        out[(n0 + half) * 10 + ht] = (float)(128 - 2 * pop) + g_sbl[ht];
    }
}

// ------------------------------ launch -------------------------------------
// Inputs identified BY ELEMENT COUNT (all 9 distinct): robust to any order.
extern "C" void kernel_launch(void* const* d_in, const int* in_sizes, int n_in,
                              void* d_out, int out_size) {
    (void)out_size;
    const float *x = 0, *w1 = 0, *w2 = 0, *w3 = 0, *wl = 0, *bl = 0;
    for (int i = 0; i < n_in; i++) {
        const float* p = (const float*)d_in[i];
        switch (in_sizes[i]) {
            case 6422528: x  = p; break;
            case 2592:    w1 = p; break;
            case 41472:   w2 = p; break;
            case 10368:   w3 = p; break;
            case 1280:    wl = p; break;
            case 10:      bl = p; break;
            default: break;   // b1/b2/b3 cancel under BN+sign
        }
    }
    prepk   <<<50,   256>>>(w1, w2, w3, wl, bl);
    binxk   <<<1024, 256>>>(x);
    conv1k  <<<1024, 256>>>();
    suma1k  <<<200,  256>>>();
    conv2k  <<<4096, 384>>>();
    suma2k  <<<72,   256>>>();
    conv34k <<<4096, 256>>>((float*)d_out);
}